// round 1
// baseline (speedup 1.0000x reference)
#include <cuda_runtime.h>
#include <math.h>

#define N_ROWS 400000
#define M_SEG  100000
#define EMB    128
#define CTX    256
#define LAT    256
#define K_MIX  (EMB + 1)        // 129
#define K_GATE (EMB + 1 + CTX)  // 385

#define BM 64
#define BN 256
#define BK 32
#define BMP (BM + 4)

// scratch (device globals — no allocation allowed)
__device__ float g_pooled[(size_t)M_SEG * K_MIX];   // segment sums [M,129]
__device__ float g_counts[M_SEG];
__device__ float g_ctx[(size_t)M_SEG * CTX];        // mixture context [M,256]

__device__ __forceinline__ float sp(float x) {
    // stable softplus: max(x,0) + log(1 + exp(-|x|)); 2 MUFU ops
    return fmaxf(x, 0.f) + __logf(1.f + __expf(-fabsf(x)));
}

// ---------------------------------------------------------------------------
__global__ void k_zero() {
    long long i = (long long)blockIdx.x * 256 + threadIdx.x;
    const long long P = (long long)M_SEG * K_MIX;
    if (i < P) g_pooled[i] = 0.f;
    else if (i < P + M_SEG) g_counts[i - P] = 0.f;
}

// one thread per (row, k); k==EMB thread also bumps count + copies mole_frac out
__global__ void k_accum(const float* __restrict__ emb,
                        const float* __restrict__ frac,
                        const int*   __restrict__ seg,
                        float* __restrict__ out_frac) {
    int idx = blockIdx.x * 256 + threadIdx.x;
    if (idx >= N_ROWS * K_MIX) return;
    int r = idx / K_MIX;
    int k = idx - r * K_MIX;
    int s = seg[r];
    float v;
    if (k < EMB) {
        v = emb[(long long)r * EMB + k];
    } else {
        v = frac[r];
        atomicAdd(&g_counts[s], 1.f);
        if (out_frac) out_frac[r] = v;
    }
    atomicAdd(&g_pooled[(long long)s * K_MIX + k], v);
}

// ---------------------------------------------------------------------------
// Fused 2-layer MLP core macro: 64x256 tile, layer1 result transposed in smem.
#define FMA_BLOCK()                                                          \
    do {                                                                     \
        float av[4] = {a.x, a.y, a.z, a.w};                                  \
        _Pragma("unroll")                                                    \
        for (int i = 0; i < 4; i++) {                                        \
            _Pragma("unroll")                                                \
            for (int j = 0; j < 4; j++) {                                    \
                acc[i][4*j+0] = fmaf(av[i], b[j].x, acc[i][4*j+0]);          \
                acc[i][4*j+1] = fmaf(av[i], b[j].y, acc[i][4*j+1]);          \
                acc[i][4*j+2] = fmaf(av[i], b[j].z, acc[i][4*j+2]);          \
                acc[i][4*j+3] = fmaf(av[i], b[j].w, acc[i][4*j+3]);          \
            }                                                                \
        }                                                                    \
    } while (0)

// ---------------- mixture MLP: pooled mean -> softplus MLP -> g_ctx --------
__global__ __launch_bounds__(256)
void k_mix(const float* __restrict__ W1, const float* __restrict__ b1,
           const float* __restrict__ W2, const float* __restrict__ b2) {
    extern __shared__ float smf[];
    float* As  = smf;                    // BK * BMP
    float* Bs  = As + BK * BMP;          // BK * BN
    float* Gt  = Bs + BK * BN;           // BN * BMP
    float* inv = Gt + BN * BMP;          // BM

    const int tid  = threadIdx.x;
    const int tcol = tid & 15;
    const int trow = tid >> 4;
    const int rowBase = blockIdx.x * BM;

    if (tid < BM) {
        int gr = rowBase + tid;
        float c = (gr < M_SEG) ? g_counts[gr] : 1.f;
        inv[tid] = 1.f / fmaxf(c, 1.f);
    }
    __syncthreads();

    float acc[4][16];
#pragma unroll
    for (int i = 0; i < 4; i++)
#pragma unroll
        for (int j = 0; j < 16; j++) acc[i][j] = 0.f;

    // layer 1: K = 129
    const int NT1 = (K_MIX + BK - 1) / BK;
    for (int t = 0; t < NT1; ++t) {
        int k0 = t * BK;
#pragma unroll
        for (int u = 0; u < 8; u++) {
            int flat = tid + u * 256;
            int r = flat >> 5, kk = flat & 31;
            int k = k0 + kk;
            int gr = rowBase + r;
            float v = 0.f;
            if (k < K_MIX && gr < M_SEG)
                v = g_pooled[(long long)gr * K_MIX + k] * inv[r];
            As[kk * BMP + r] = v;
        }
#pragma unroll
        for (int u = 0; u < 8; u++) {
            int flat = tid + u * 256;
            int kk = flat >> 6, c4 = flat & 63;
            int k = k0 + kk;
            float4 v = make_float4(0.f, 0.f, 0.f, 0.f);
            if (k < K_MIX) v = *(const float4*)&W1[(long long)k * BN + c4 * 4];
            *(float4*)&Bs[kk * BN + c4 * 4] = v;
        }
        __syncthreads();
#pragma unroll
        for (int kk = 0; kk < BK; ++kk) {
            float4 a = *(const float4*)&As[kk * BMP + trow * 4];
            float4 b[4];
#pragma unroll
            for (int j = 0; j < 4; j++)
                b[j] = *(const float4*)&Bs[kk * BN + tcol * 4 + 64 * j];
            FMA_BLOCK();
        }
        __syncthreads();
    }
    // epilogue 1 -> Gt transposed
#pragma unroll
    for (int j = 0; j < 4; j++)
#pragma unroll
        for (int v = 0; v < 4; v++) {
            int col = tcol * 4 + 64 * j + v;
            float bb = __ldg(&b1[col]);
#pragma unroll
            for (int i = 0; i < 4; i++) {
                Gt[col * BMP + trow * 4 + i] = sp(acc[i][4*j+v] + bb);
                acc[i][4*j+v] = 0.f;
            }
        }

    // layer 2: K = 256
    for (int t = 0; t < CTX / BK; ++t) {
        int k0 = t * BK;
#pragma unroll
        for (int u = 0; u < 8; u++) {
            int flat = tid + u * 256;
            int kk = flat >> 6, c4 = flat & 63;
            *(float4*)&Bs[kk * BN + c4 * 4] =
                *(const float4*)&W2[(long long)(k0 + kk) * BN + c4 * 4];
        }
        __syncthreads();
#pragma unroll
        for (int kk = 0; kk < BK; ++kk) {
            float4 a = *(const float4*)&Gt[(k0 + kk) * BMP + trow * 4];
            float4 b[4];
#pragma unroll
            for (int j = 0; j < 4; j++)
                b[j] = *(const float4*)&Bs[kk * BN + tcol * 4 + 64 * j];
            FMA_BLOCK();
        }
        __syncthreads();
    }
    // epilogue 2 -> g_ctx
#pragma unroll
    for (int i = 0; i < 4; i++) {
        int gr = rowBase + trow * 4 + i;
        if (gr >= M_SEG) continue;
#pragma unroll
        for (int j = 0; j < 4; j++) {
            int col = tcol * 4 + 64 * j;
            float4 o;
            o.x = sp(acc[i][4*j+0] + __ldg(&b2[col+0]));
            o.y = sp(acc[i][4*j+1] + __ldg(&b2[col+1]));
            o.z = sp(acc[i][4*j+2] + __ldg(&b2[col+2]));
            o.w = sp(acc[i][4*j+3] + __ldg(&b2[col+3]));
            *(float4*)&g_ctx[(long long)gr * CTX + col] = o;
        }
    }
}

// ---------------- gate MLP: [emb|frac|ctx[seg]] -> 2-layer MLP -> out ------
__global__ __launch_bounds__(256)
void k_gate(const float* __restrict__ emb, const float* __restrict__ frac,
            const int*   __restrict__ seg,
            const float* __restrict__ W1, const float* __restrict__ b1,
            const float* __restrict__ W2, const float* __restrict__ b2,
            float* __restrict__ out) {
    extern __shared__ float smf[];
    float* As  = smf;
    float* Bs  = As + BK * BMP;
    float* Gt  = Bs + BK * BN;
    int*   sgs = (int*)(Gt + BN * BMP);

    const int tid  = threadIdx.x;
    const int tcol = tid & 15;
    const int trow = tid >> 4;
    const int rowBase = blockIdx.x * BM;

    if (tid < BM) sgs[tid] = seg[rowBase + tid];
    __syncthreads();

    float acc[4][16];
#pragma unroll
    for (int i = 0; i < 4; i++)
#pragma unroll
        for (int j = 0; j < 16; j++) acc[i][j] = 0.f;

    // layer 1: K = 385
    const int NT1 = (K_GATE + BK - 1) / BK;
    for (int t = 0; t < NT1; ++t) {
        int k0 = t * BK;
#pragma unroll
        for (int u = 0; u < 8; u++) {
            int flat = tid + u * 256;
            int r = flat >> 5, kk = flat & 31;
            int k = k0 + kk;
            float v = 0.f;
            if (k < K_GATE) {
                int gr = rowBase + r;
                if (k < EMB)       v = emb[(long long)gr * EMB + k];
                else if (k == EMB) v = frac[gr];
                else               v = g_ctx[(long long)sgs[r] * CTX + (k - EMB - 1)];
            }
            As[kk * BMP + r] = v;
        }
#pragma unroll
        for (int u = 0; u < 8; u++) {
            int flat = tid + u * 256;
            int kk = flat >> 6, c4 = flat & 63;
            int k = k0 + kk;
            float4 v = make_float4(0.f, 0.f, 0.f, 0.f);
            if (k < K_GATE) v = *(const float4*)&W1[(long long)k * BN + c4 * 4];
            *(float4*)&Bs[kk * BN + c4 * 4] = v;
        }
        __syncthreads();
#pragma unroll
        for (int kk = 0; kk < BK; ++kk) {
            float4 a = *(const float4*)&As[kk * BMP + trow * 4];
            float4 b[4];
#pragma unroll
            for (int j = 0; j < 4; j++)
                b[j] = *(const float4*)&Bs[kk * BN + tcol * 4 + 64 * j];
            FMA_BLOCK();
        }
        __syncthreads();
    }
    // epilogue 1 -> Gt transposed
#pragma unroll
    for (int j = 0; j < 4; j++)
#pragma unroll
        for (int v = 0; v < 4; v++) {
            int col = tcol * 4 + 64 * j + v;
            float bb = __ldg(&b1[col]);
#pragma unroll
            for (int i = 0; i < 4; i++) {
                Gt[col * BMP + trow * 4 + i] = sp(acc[i][4*j+v] + bb);
                acc[i][4*j+v] = 0.f;
            }
        }

    // layer 2: K = 256
    for (int t = 0; t < LAT / BK; ++t) {
        int k0 = t * BK;
#pragma unroll
        for (int u = 0; u < 8; u++) {
            int flat = tid + u * 256;
            int kk = flat >> 6, c4 = flat & 63;
            *(float4*)&Bs[kk * BN + c4 * 4] =
                *(const float4*)&W2[(long long)(k0 + kk) * BN + c4 * 4];
        }
        __syncthreads();
#pragma unroll
        for (int kk = 0; kk < BK; ++kk) {
            float4 a = *(const float4*)&Gt[(k0 + kk) * BMP + trow * 4];
            float4 b[4];
#pragma unroll
            for (int j = 0; j < 4; j++)
                b[j] = *(const float4*)&Bs[kk * BN + tcol * 4 + 64 * j];
            FMA_BLOCK();
        }
        __syncthreads();
    }
    // epilogue 2 -> out (latent)
#pragma unroll
    for (int i = 0; i < 4; i++) {
        int gr = rowBase + trow * 4 + i;
#pragma unroll
        for (int j = 0; j < 4; j++) {
            int col = tcol * 4 + 64 * j;
            float4 o;
            o.x = sp(acc[i][4*j+0] + __ldg(&b2[col+0]));
            o.y = sp(acc[i][4*j+1] + __ldg(&b2[col+1]));
            o.z = sp(acc[i][4*j+2] + __ldg(&b2[col+2]));
            o.w = sp(acc[i][4*j+3] + __ldg(&b2[col+3]));
            *(float4*)&out[(long long)gr * LAT + col] = o;
        }
    }
}

// ---------------------------------------------------------------------------
extern "C" void kernel_launch(void* const* d_in, const int* in_sizes, int n_in,
                              void* d_out, int out_size) {
    const float* emb  = (const float*)d_in[0];
    const float* frac = (const float*)d_in[1];
    const int*   seg  = (const int*)  d_in[2];
    const float* iW1  = (const float*)d_in[3];
    const float* ib1  = (const float*)d_in[4];
    const float* iW2  = (const float*)d_in[5];
    const float* ib2  = (const float*)d_in[6];
    const float* gW1  = (const float*)d_in[7];
    const float* gb1  = (const float*)d_in[8];
    const float* gW2  = (const float*)d_in[9];
    const float* gb2  = (const float*)d_in[10];
    float* out = (float*)d_out;

    const int smemB = (BK * BMP + BK * BN + BN * BMP + BM) * (int)sizeof(float);
    cudaFuncSetAttribute(k_mix,  cudaFuncAttributeMaxDynamicSharedMemorySize, smemB);
    cudaFuncSetAttribute(k_gate, cudaFuncAttributeMaxDynamicSharedMemorySize, smemB);

    long long totz = (long long)M_SEG * K_MIX + M_SEG;
    k_zero<<<(unsigned)((totz + 255) / 256), 256>>>();

    float* out_frac = nullptr;
    if ((long long)out_size >= (long long)N_ROWS * (LAT + 1))
        out_frac = out + (size_t)N_ROWS * LAT;

    long long tota = (long long)N_ROWS * K_MIX;
    k_accum<<<(unsigned)((tota + 255) / 256), 256>>>(emb, frac, seg, out_frac);

    k_mix<<<(M_SEG + BM - 1) / BM, 256, smemB>>>(iW1, ib1, iW2, ib2);
    k_gate<<<N_ROWS / BM, 256, smemB>>>(emb, frac, seg, gW1, gb1, gW2, gb2, out);
}

// round 5
// speedup vs baseline: 2.3671x; 2.3671x over previous
#include <cuda_runtime.h>
#include <cuda_bf16.h>
#include <cstdint>
#include <math.h>

#define N_ROWS 400000
#define M_SEG  100000
#define EMB    128
#define CTX    256
#define LAT    256
#define K_MIX  129
#define PSTR   132

// smem layout (bytes)
#define OFF_B1S   0        // bias1: 256 f32
#define OFF_B2S   1024     // bias2: 256 f32
#define OFF_AUX   2048     // 128 ints/floats
#define OFF_A1    4096     // A1 hi 10240 | lo 10240  -> end 24576
#define OFF_B0    24576    // B buf0: hi 20480 | lo 20480 -> end 65536
#define OFF_B1B   65536    // B buf1 -> end 106496
#define OFF_A2    4096     // A2 hi 67584 | lo 67584 -> end 139264 (phase 2)
#define A2_HL     67584
#define OFF_B20   139264   // phase-2 B buf0 -> 180224
#define OFF_B21   180224   // phase-2 B buf1 -> 221184
#define SMEM_TOTAL 221184

// scratch globals
__device__ float g_pooled[(size_t)M_SEG * PSTR];
__device__ float g_counts[M_SEG];
__device__ float g_ctx[(size_t)M_SEG * CTX];
// prepped B chunk images: [chunk][256][40] bf16, hi & lo
__device__ __align__(16) __nv_bfloat16 g_gw1h[13*10240], g_gw1l[13*10240];
__device__ __align__(16) __nv_bfloat16 g_gw2h[8*10240],  g_gw2l[8*10240];
__device__ __align__(16) __nv_bfloat16 g_mw1h[5*10240],  g_mw1l[5*10240];
__device__ __align__(16) __nv_bfloat16 g_mw2h[8*10240],  g_mw2l[8*10240];

__device__ __forceinline__ uint32_t smem_u32(const void* p) {
    uint32_t a;
    asm("{ .reg .u64 t; cvta.to.shared.u64 t, %1; cvt.u32.u64 %0, t; }" : "=r"(a) : "l"(p));
    return a;
}
#define LDSM4(r0,r1,r2,r3,addr) \
    asm volatile("ldmatrix.sync.aligned.m8n8.x4.shared.b16 {%0,%1,%2,%3}, [%4];" \
        : "=r"(r0),"=r"(r1),"=r"(r2),"=r"(r3) : "r"(addr))
#define MMA(d,a,b0,b1) \
    asm volatile("mma.sync.aligned.m16n8k16.row.col.f32.bf16.bf16.f32 " \
        "{%0,%1,%2,%3},{%4,%5,%6,%7},{%8,%9},{%0,%1,%2,%3};" \
        : "+f"((d)[0]),"+f"((d)[1]),"+f"((d)[2]),"+f"((d)[3]) \
        : "r"((a)[0]),"r"((a)[1]),"r"((a)[2]),"r"((a)[3]),"r"(b0),"r"(b1))
#define CP16(sa,gp) asm volatile("cp.async.cg.shared.global [%0], [%1], 16;" :: "r"(sa),"l"(gp))
#define CP_COMMIT() asm volatile("cp.async.commit_group;" ::: "memory")
#define CP_WAIT0()  asm volatile("cp.async.wait_group 0;" ::: "memory")
#define CP_WAIT1()  asm volatile("cp.async.wait_group 1;" ::: "memory")
#define STS32(a,v)  asm volatile("st.shared.b32 [%0], %1;" :: "r"(a),"r"(v) : "memory")
#define STSV2(a,x,y) asm volatile("st.shared.v2.b32 [%0], {%1,%2};" :: "r"(a),"r"(x),"r"(y) : "memory")

__device__ __forceinline__ float sp(float x) {
    return fmaxf(x, 0.f) + __logf(1.f + __expf(-fabsf(x)));
}
__device__ __forceinline__ void split2(float a, float b, uint32_t& hp, uint32_t& lp) {
    __nv_bfloat16 ha = __float2bfloat16_rn(a), hb = __float2bfloat16_rn(b);
    float la = a - __bfloat162float(ha), lb = b - __bfloat162float(hb);
    __nv_bfloat162 hv = __halves2bfloat162(ha, hb);
    __nv_bfloat162 lv = __floats2bfloat162_rn(la, lb);
    hp = *(uint32_t*)&hv; lp = *(uint32_t*)&lv;
}

// ---------------------------------------------------------------------------
__global__ void k_zero() {
    long long i = (long long)blockIdx.x * 256 + threadIdx.x;
    const long long P = (long long)M_SEG * PSTR;
    if (i < P) g_pooled[i] = 0.f;
    else if (i < P + M_SEG) g_counts[i - P] = 0.f;
}

__global__ void k_accum(const float* __restrict__ emb, const float* __restrict__ frac,
                        const int* __restrict__ seg, float* __restrict__ out_frac) {
    int idx = blockIdx.x * 256 + threadIdx.x;
    if (idx >= N_ROWS * K_MIX) return;
    int r = idx / K_MIX;
    int k = idx - r * K_MIX;
    int s = seg[r];
    float v;
    if (k < EMB) v = emb[(long long)r * EMB + k];
    else {
        v = frac[r];
        atomicAdd(&g_counts[s], 1.f);
        if (out_frac) out_frac[r] = v;
    }
    atomicAdd(&g_pooled[(long long)s * PSTR + k], v);
}

// prep: W[Ksrc][256] -> chunk images [c][n][kk] bf16 hi/lo (kk pad 40, zero)
__global__ void k_prep(const float* __restrict__ W, int mode, int nch, int Kreal, int which) {
    __nv_bfloat16 *dh, *dl;
    if (which == 0)      { dh = g_gw1h; dl = g_gw1l; }
    else if (which == 1) { dh = g_gw2h; dl = g_gw2l; }
    else if (which == 2) { dh = g_mw1h; dl = g_mw1l; }
    else                 { dh = g_mw2h; dl = g_mw2l; }
    int idx = blockIdx.x * 256 + threadIdx.x;
    if (idx >= nch * 10240) return;
    int c = idx / 10240, rem = idx - c * 10240;
    int n = rem / 40, kk = rem - n * 40;
    float v = 0.f;
    if (kk < 32) {
        int kg = c * 32 + kk, sr;
        if (mode == 1) sr = kg < 128 ? kg : (kg < 384 ? kg + 1 : (kg == 384 ? 128 : -1));
        else           sr = (kg < Kreal) ? kg : -1;
        if (sr >= 0) v = W[(long long)sr * 256 + n];
    }
    __nv_bfloat16 h = __float2bfloat16_rn(v);
    dh[idx] = h;
    dl[idx] = __float2bfloat16_rn(v - __bfloat162float(h));
}

// ---------------------------------------------------------------------------
__device__ __forceinline__ void cp_chunk(uint32_t dH, uint32_t dL,
                                         const __nv_bfloat16* sH, const __nv_bfloat16* sL,
                                         int c, int tid) {
    const uint4* gh = (const uint4*)sH + (long long)c * 1280;
    const uint4* gl = (const uint4*)sL + (long long)c * 1280;
#pragma unroll
    for (int j = 0; j < 5; j++) {
        int i = tid + j * 256;
        CP16(dH + i * 16, gh + i);
        CP16(dL + i * 16, gl + i);
    }
}

__device__ __forceinline__ void mma_chunk(float (&acc)[2][16][4],
                                          uint32_t aH, uint32_t aL, int aStride,
                                          uint32_t bH, uint32_t bL,
                                          int lane, int m0, int n0w) {
    const int arow = (lane & 7) + ((lane >> 3) & 1) * 8;
    const int brow = (lane & 7) + (lane >> 4) * 8;
    const int bk0  = ((lane >> 3) & 1) * 16;
#pragma unroll
    for (int ks = 0; ks < 2; ks++) {
        uint32_t ah[2][4], al[2][4];
        int akb = ks * 32 + (lane >> 4) * 16;
#pragma unroll
        for (int mi = 0; mi < 2; mi++) {
            uint32_t ra = aH + (uint32_t)(m0 + mi * 16 + arow) * aStride + akb;
            LDSM4(ah[mi][0], ah[mi][1], ah[mi][2], ah[mi][3], ra);
            uint32_t rl = aL + (uint32_t)(m0 + mi * 16 + arow) * aStride + akb;
            LDSM4(al[mi][0], al[mi][1], al[mi][2], al[mi][3], rl);
        }
        int bkb = ks * 32 + bk0;
#pragma unroll
        for (int g = 0; g < 8; g++) {
            uint32_t bh[4], bl[4];
            uint32_t ro = (uint32_t)(n0w + g * 16 + brow) * 80 + bkb;
            LDSM4(bh[0], bh[1], bh[2], bh[3], bH + ro);
            LDSM4(bl[0], bl[1], bl[2], bl[3], bL + ro);
#pragma unroll
            for (int mi = 0; mi < 2; mi++) {
                MMA(acc[mi][2*g],   ah[mi], bh[0], bh[1]);
                MMA(acc[mi][2*g+1], ah[mi], bh[2], bh[3]);
                MMA(acc[mi][2*g],   al[mi], bh[0], bh[1]);
                MMA(acc[mi][2*g+1], al[mi], bh[2], bh[3]);
                MMA(acc[mi][2*g],   ah[mi], bl[0], bl[1]);
                MMA(acc[mi][2*g+1], ah[mi], bl[2], bl[3]);
            }
        }
    }
}

template<int GATE>
__global__ __launch_bounds__(256, 1)
void k_mlp(const float* __restrict__ emb, const float* __restrict__ frac,
           const int* __restrict__ seg,
           const float* __restrict__ b1v, const float* __restrict__ b2v,
           float* __restrict__ outp) {
    extern __shared__ __align__(16) char sm[];
    const uint32_t sb = smem_u32(sm);
    const int tid = threadIdx.x, w = tid >> 5, lane = tid & 31;
    const int m0 = (w & 3) * 32, n0w = (w >> 2) * 128;
    const int rowBase = blockIdx.x * 128;
    constexpr int CH1 = GATE ? 13 : 5;
    constexpr int CH2 = 8;

    float* bias1s = (float*)(sm + OFF_B1S);
    float* bias2s = (float*)(sm + OFF_B2S);
    int*   axseg  = (int*)  (sm + OFF_AUX);
    float* axinv  = (float*)(sm + OFF_AUX);

    bias1s[tid] = b1v[tid];
    bias2s[tid] = b2v[tid];
    if (tid < 128) {
        if (GATE) axseg[tid] = seg[rowBase + tid];
        else {
            int gr = rowBase + tid;
            float c = (gr < M_SEG) ? g_counts[gr] : 1.f;
            axinv[tid] = 1.f / fmaxf(c, 1.f);
        }
    }
    __syncthreads();

    const __nv_bfloat16* w1h = GATE ? g_gw1h : g_mw1h;
    const __nv_bfloat16* w1l = GATE ? g_gw1l : g_mw1l;
    const __nv_bfloat16* w2h = GATE ? g_gw2h : g_mw2h;
    const __nv_bfloat16* w2l = GATE ? g_gw2l : g_mw2l;

    float acc[2][16][4];
#pragma unroll
    for (int i = 0; i < 2; i++)
#pragma unroll
        for (int j = 0; j < 16; j++)
#pragma unroll
            for (int q = 0; q < 4; q++) acc[i][j][q] = 0.f;

    // ---------------- phase 1 ----------------
    cp_chunk(sb + OFF_B0, sb + OFF_B0 + 20480, w1h, w1l, 0, tid);
    CP_COMMIT();

    for (int c = 0; c < CH1; ++c) {
        { // gather A chunk -> A1 hi/lo
            const int r = tid >> 1, half = tid & 1, rg = rowBase + r;
#pragma unroll
            for (int i = 0; i < 4; i++) {
                int kk = half * 16 + i * 4;
                int k = c * 32 + kk;
                float4 v = make_float4(0.f, 0.f, 0.f, 0.f);
                if (GATE) {
                    if (c < 4) v = *(const float4*)&emb[(long long)rg * EMB + k];
                    else if (c < 12) {
                        int s = axseg[r];
                        v = *(const float4*)&g_ctx[(long long)s * CTX + (k - 128)];
                    } else if (kk == 0) v.x = frac[rg];
                } else {
                    if (rg < M_SEG) {
                        float inv = axinv[r];
                        if (c < 4) {
                            v = *(const float4*)&g_pooled[(long long)rg * PSTR + k];
                            v.x *= inv; v.y *= inv; v.z *= inv; v.w *= inv;
                        } else if (kk == 0) {
                            v.x = g_pooled[(long long)rg * PSTR + 128] * inv;
                        }
                    }
                }
                uint32_t h01, l01, h23, l23;
                split2(v.x, v.y, h01, l01);
                split2(v.z, v.w, h23, l23);
                uint32_t off = (uint32_t)r * 80 + (uint32_t)kk * 2;
                STSV2(sb + OFF_A1 + off, h01, h23);
                STSV2(sb + OFF_A1 + 10240 + off, l01, l23);
            }
        }
        uint32_t curB = (c & 1) ? OFF_B1B : OFF_B0;
        if (c + 1 < CH1) {
            uint32_t nxtB = ((c + 1) & 1) ? OFF_B1B : OFF_B0;
            cp_chunk(sb + nxtB, sb + nxtB + 20480, w1h, w1l, c + 1, tid);
            CP_COMMIT();
            CP_WAIT1();
        } else CP_WAIT0();
        __syncthreads();
        mma_chunk(acc, sb + OFF_A1, sb + OFF_A1 + 10240, 80,
                  sb + curB, sb + curB + 20480, lane, m0, n0w);
        __syncthreads();
    }

    // prefetch phase-2 chunk 0 early
    cp_chunk(sb + OFF_B20, sb + OFF_B20 + 20480, w2h, w2l, 0, tid);
    CP_COMMIT();

    // ---------------- epilogue 1: acc -> softplus -> A2 hi/lo ----------------
    {
        const int rb = m0 + (lane >> 2);
        const int cb = n0w + (lane & 3) * 2;
#pragma unroll
        for (int mi = 0; mi < 2; mi++)
#pragma unroll
            for (int ni = 0; ni < 16; ni++) {
                int col = cb + ni * 8;
                float2 bb = *(float2*)&bias1s[col];
                int row = rb + mi * 16;
                uint32_t ad = sb + OFF_A2 + (uint32_t)row * 528 + (uint32_t)col * 2;
                uint32_t hp, lp;
                float y0 = sp(acc[mi][ni][0] + bb.x), y1 = sp(acc[mi][ni][1] + bb.y);
                split2(y0, y1, hp, lp);
                STS32(ad, hp); STS32(ad + A2_HL, lp);
                float y2 = sp(acc[mi][ni][2] + bb.x), y3 = sp(acc[mi][ni][3] + bb.y);
                split2(y2, y3, hp, lp);
                STS32(ad + 8 * 528, hp); STS32(ad + 8 * 528 + A2_HL, lp);
                acc[mi][ni][0] = acc[mi][ni][1] = acc[mi][ni][2] = acc[mi][ni][3] = 0.f;
            }
    }

    // ---------------- phase 2 ----------------
    for (int c = 0; c < CH2; ++c) {
        uint32_t curB = (c & 1) ? OFF_B21 : OFF_B20;
        if (c + 1 < CH2) {
            uint32_t nxtB = ((c + 1) & 1) ? OFF_B21 : OFF_B20;
            cp_chunk(sb + nxtB, sb + nxtB + 20480, w2h, w2l, c + 1, tid);
            CP_COMMIT();
            CP_WAIT1();
        } else CP_WAIT0();
        __syncthreads();
        // BUGFIX (round 4): advance A base by c*32 K-columns (c*64 bytes)
        mma_chunk(acc, sb + OFF_A2 + (uint32_t)c * 64,
                  sb + OFF_A2 + A2_HL + (uint32_t)c * 64, 528,
                  sb + curB, sb + curB + 20480, lane, m0, n0w);
        __syncthreads();
    }

    // ---------------- epilogue 2: acc -> softplus -> out ----------------
    {
        float* dst = GATE ? outp : g_ctx;
        const int rb = m0 + (lane >> 2);
        const int cb = n0w + (lane & 3) * 2;
#pragma unroll
        for (int mi = 0; mi < 2; mi++)
#pragma unroll
            for (int ni = 0; ni < 16; ni++) {
                int col = cb + ni * 8;
                float2 bb = *(float2*)&bias2s[col];
                int row = rb + mi * 16;
                int gr = rowBase + row;
                float y0 = sp(acc[mi][ni][0] + bb.x), y1 = sp(acc[mi][ni][1] + bb.y);
                if (GATE || gr < M_SEG)
                    *(float2*)&dst[(long long)gr * 256 + col] = make_float2(y0, y1);
                float y2 = sp(acc[mi][ni][2] + bb.x), y3 = sp(acc[mi][ni][3] + bb.y);
                if (GATE || gr + 8 < M_SEG)
                    *(float2*)&dst[(long long)(gr + 8) * 256 + col] = make_float2(y2, y3);
            }
    }
}

// ---------------------------------------------------------------------------
extern "C" void kernel_launch(void* const* d_in, const int* in_sizes, int n_in,
                              void* d_out, int out_size) {
    const float* emb  = (const float*)d_in[0];
    const float* frac = (const float*)d_in[1];
    const int*   seg  = (const int*)  d_in[2];
    const float* iW1  = (const float*)d_in[3];
    const float* ib1  = (const float*)d_in[4];
    const float* iW2  = (const float*)d_in[5];
    const float* ib2  = (const float*)d_in[6];
    const float* gW1  = (const float*)d_in[7];
    const float* gb1  = (const float*)d_in[8];
    const float* gW2  = (const float*)d_in[9];
    const float* gb2  = (const float*)d_in[10];
    float* out = (float*)d_out;

    cudaFuncSetAttribute(k_mlp<0>, cudaFuncAttributeMaxDynamicSharedMemorySize, SMEM_TOTAL);
    cudaFuncSetAttribute(k_mlp<1>, cudaFuncAttributeMaxDynamicSharedMemorySize, SMEM_TOTAL);

    k_prep<<<(13*10240 + 255)/256, 256>>>(gW1, 1, 13, 385, 0);
    k_prep<<<(8*10240  + 255)/256, 256>>>(gW2, 0, 8, 256, 1);
    k_prep<<<(5*10240  + 255)/256, 256>>>(iW1, 0, 5, 129, 2);
    k_prep<<<(8*10240  + 255)/256, 256>>>(iW2, 0, 8, 256, 3);

    long long totz = (long long)M_SEG * PSTR + M_SEG;
    k_zero<<<(unsigned)((totz + 255)/256), 256>>>();

    float* out_frac = nullptr;
    if ((long long)out_size >= (long long)N_ROWS * (LAT + 1))
        out_frac = out + (size_t)N_ROWS * LAT;
    long long tota = (long long)N_ROWS * K_MIX;
    k_accum<<<(unsigned)((tota + 255)/256), 256>>>(emb, frac, seg, out_frac);

    k_mlp<0><<<(M_SEG + 127)/128, 256, SMEM_TOTAL>>>(emb, frac, seg, ib1, ib2, nullptr);
    k_mlp<1><<<N_ROWS / 128, 256, SMEM_TOTAL>>>(emb, frac, seg, gb1, gb2, out);
}

// round 6
// speedup vs baseline: 3.0691x; 1.2965x over previous
#include <cuda_runtime.h>
#include <cuda_fp16.h>
#include <cstdint>
#include <math.h>

#define N_ROWS 400000
#define M_SEG  100000
#define EMB    128
#define CTX    256
#define LAT    256
#define K_MIX  129
#define PSTR   132

// smem layout (bytes)
#define OFF_B1S   0        // bias1: 256 f32
#define OFF_B2S   1024     // bias2: 256 f32
#define OFF_AUX   2048     // 128 ints/floats
#define OFF_A1    4096     // A1 hi 10240 | lo 10240 -> end 24576
#define OFF_B0    24576    // B buf0: 20480 -> end 45056
#define OFF_B1B   45056    // B buf1: 20480 -> end 65536
#define OFF_A2    4096     // A2 hi 67584 | lo 67584 -> end 139264 (phase 2)
#define A2_HL     67584
#define OFF_B20   139264   // phase-2 B buf0 -> 159744
#define OFF_B21   159744   // phase-2 B buf1 -> 180224
#define SMEM_TOTAL 180224

// scratch globals
__device__ float g_pooled[(size_t)M_SEG * PSTR];
__device__ float g_counts[M_SEG];
__device__ float g_ctx[(size_t)M_SEG * CTX];
// prepped B chunk images: [chunk][256][40] fp16 (single, RN)
__device__ __align__(16) __half g_gw1[13*10240];
__device__ __align__(16) __half g_gw2[8*10240];
__device__ __align__(16) __half g_mw1[5*10240];
__device__ __align__(16) __half g_mw2[8*10240];

__device__ __forceinline__ uint32_t smem_u32(const void* p) {
    uint32_t a;
    asm("{ .reg .u64 t; cvta.to.shared.u64 t, %1; cvt.u32.u64 %0, t; }" : "=r"(a) : "l"(p));
    return a;
}
#define LDSM4(r0,r1,r2,r3,addr) \
    asm volatile("ldmatrix.sync.aligned.m8n8.x4.shared.b16 {%0,%1,%2,%3}, [%4];" \
        : "=r"(r0),"=r"(r1),"=r"(r2),"=r"(r3) : "r"(addr))
#define MMA(d,a,b0,b1) \
    asm volatile("mma.sync.aligned.m16n8k16.row.col.f32.f16.f16.f32 " \
        "{%0,%1,%2,%3},{%4,%5,%6,%7},{%8,%9},{%0,%1,%2,%3};" \
        : "+f"((d)[0]),"+f"((d)[1]),"+f"((d)[2]),"+f"((d)[3]) \
        : "r"((a)[0]),"r"((a)[1]),"r"((a)[2]),"r"((a)[3]),"r"(b0),"r"(b1))
#define CP16(sa,gp) asm volatile("cp.async.cg.shared.global [%0], [%1], 16;" :: "r"(sa),"l"(gp))
#define CP_COMMIT() asm volatile("cp.async.commit_group;" ::: "memory")
#define CP_WAIT0()  asm volatile("cp.async.wait_group 0;" ::: "memory")
#define CP_WAIT1()  asm volatile("cp.async.wait_group 1;" ::: "memory")
#define STS32(a,v)  asm volatile("st.shared.b32 [%0], %1;" :: "r"(a),"r"(v) : "memory")
#define STSV2(a,x,y) asm volatile("st.shared.v2.b32 [%0], {%1,%2};" :: "r"(a),"r"(x),"r"(y) : "memory")

__device__ __forceinline__ float sp(float x) {
    return fmaxf(x, 0.f) + __logf(1.f + __expf(-fabsf(x)));
}
// fp16 hi/lo split of two fp32 values -> packed half2 hi + half2 lo
__device__ __forceinline__ void split2(float a, float b, uint32_t& hp, uint32_t& lp) {
    __half ha = __float2half_rn(a), hb = __float2half_rn(b);
    float la = a - __half2float(ha), lb = b - __half2float(hb);
    __half2 hv = __halves2half2(ha, hb);
    __half2 lv = __floats2half2_rn(la, lb);
    hp = *(uint32_t*)&hv; lp = *(uint32_t*)&lv;
}

// ---------------------------------------------------------------------------
__global__ void k_zero() {
    long long i = (long long)blockIdx.x * 256 + threadIdx.x;
    const long long P = (long long)M_SEG * PSTR;
    if (i < P) g_pooled[i] = 0.f;
    else if (i < P + M_SEG) g_counts[i - P] = 0.f;
}

// one thread per (row, float4-group); group 32 = frac + count
__global__ void k_accum(const float* __restrict__ emb, const float* __restrict__ frac,
                        const int* __restrict__ seg, float* __restrict__ out_frac) {
    int idx = blockIdx.x * 256 + threadIdx.x;
    if (idx >= N_ROWS * 33) return;
    int r = idx / 33;
    int g = idx - r * 33;
    int s = seg[r];
    if (g < 32) {
        float4 v = *(const float4*)&emb[(long long)r * EMB + g * 4];
        float* dst = &g_pooled[(long long)s * PSTR + g * 4];
        atomicAdd(dst + 0, v.x);
        atomicAdd(dst + 1, v.y);
        atomicAdd(dst + 2, v.z);
        atomicAdd(dst + 3, v.w);
    } else {
        float f = frac[r];
        atomicAdd(&g_pooled[(long long)s * PSTR + 128], f);
        atomicAdd(&g_counts[s], 1.f);
        if (out_frac) out_frac[r] = f;
    }
}

// prep: W[Ksrc][256] -> chunk images [c][n][kk] fp16 RN (kk pad 40, zero)
__global__ void k_prep(const float* __restrict__ W, int mode, int nch, int Kreal, int which) {
    __half* dh;
    if (which == 0)      dh = g_gw1;
    else if (which == 1) dh = g_gw2;
    else if (which == 2) dh = g_mw1;
    else                 dh = g_mw2;
    int idx = blockIdx.x * 256 + threadIdx.x;
    if (idx >= nch * 10240) return;
    int c = idx / 10240, rem = idx - c * 10240;
    int n = rem / 40, kk = rem - n * 40;
    float v = 0.f;
    if (kk < 32) {
        int kg = c * 32 + kk, sr;
        if (mode == 1) sr = kg < 128 ? kg : (kg < 384 ? kg + 1 : (kg == 384 ? 128 : -1));
        else           sr = (kg < Kreal) ? kg : -1;
        if (sr >= 0) v = W[(long long)sr * 256 + n];
    }
    dh[idx] = __float2half_rn(v);
}

// ---------------------------------------------------------------------------
__device__ __forceinline__ void cp_chunk(uint32_t dst, const __half* src, int c, int tid) {
    const uint4* gp = (const uint4*)src + (long long)c * 1280;
#pragma unroll
    for (int j = 0; j < 5; j++) {
        int i = tid + j * 256;
        CP16(dst + i * 16, gp + i);
    }
}

__device__ __forceinline__ void mma_chunk(float (&acc)[2][16][4],
                                          uint32_t aH, uint32_t aL, int aStride,
                                          uint32_t bH,
                                          int lane, int m0, int n0w) {
    const int arow = (lane & 7) + ((lane >> 3) & 1) * 8;
    const int brow = (lane & 7) + (lane >> 4) * 8;
    const int bk0  = ((lane >> 3) & 1) * 16;
#pragma unroll
    for (int ks = 0; ks < 2; ks++) {
        uint32_t ah[2][4], al[2][4];
        int akb = ks * 32 + (lane >> 4) * 16;
#pragma unroll
        for (int mi = 0; mi < 2; mi++) {
            uint32_t ra = aH + (uint32_t)(m0 + mi * 16 + arow) * aStride + akb;
            LDSM4(ah[mi][0], ah[mi][1], ah[mi][2], ah[mi][3], ra);
            uint32_t rl = aL + (uint32_t)(m0 + mi * 16 + arow) * aStride + akb;
            LDSM4(al[mi][0], al[mi][1], al[mi][2], al[mi][3], rl);
        }
        int bkb = ks * 32 + bk0;
#pragma unroll
        for (int g = 0; g < 8; g++) {
            uint32_t bh[4];
            uint32_t ro = (uint32_t)(n0w + g * 16 + brow) * 80 + bkb;
            LDSM4(bh[0], bh[1], bh[2], bh[3], bH + ro);
#pragma unroll
            for (int mi = 0; mi < 2; mi++) {
                MMA(acc[mi][2*g],   ah[mi], bh[0], bh[1]);
                MMA(acc[mi][2*g+1], ah[mi], bh[2], bh[3]);
                MMA(acc[mi][2*g],   al[mi], bh[0], bh[1]);
                MMA(acc[mi][2*g+1], al[mi], bh[2], bh[3]);
            }
        }
    }
}

template<int GATE>
__global__ __launch_bounds__(256, 1)
void k_mlp(const float* __restrict__ emb, const float* __restrict__ frac,
           const int* __restrict__ seg,
           const float* __restrict__ b1v, const float* __restrict__ b2v,
           float* __restrict__ outp) {
    extern __shared__ __align__(16) char sm[];
    const uint32_t sb = smem_u32(sm);
    const int tid = threadIdx.x, w = tid >> 5, lane = tid & 31;
    const int m0 = (w & 3) * 32, n0w = (w >> 2) * 128;
    const int rowBase = blockIdx.x * 128;
    constexpr int CH1 = GATE ? 13 : 5;
    constexpr int CH2 = 8;

    float* bias1s = (float*)(sm + OFF_B1S);
    float* bias2s = (float*)(sm + OFF_B2S);
    int*   axseg  = (int*)  (sm + OFF_AUX);
    float* axinv  = (float*)(sm + OFF_AUX);

    bias1s[tid] = b1v[tid];
    bias2s[tid] = b2v[tid];
    if (tid < 128) {
        if (GATE) axseg[tid] = seg[rowBase + tid];
        else {
            int gr = rowBase + tid;
            float c = (gr < M_SEG) ? g_counts[gr] : 1.f;
            axinv[tid] = 1.f / fmaxf(c, 1.f);
        }
    }
    __syncthreads();

    const __half* w1 = GATE ? g_gw1 : g_mw1;
    const __half* w2 = GATE ? g_gw2 : g_mw2;

    float acc[2][16][4];
#pragma unroll
    for (int i = 0; i < 2; i++)
#pragma unroll
        for (int j = 0; j < 16; j++)
#pragma unroll
            for (int q = 0; q < 4; q++) acc[i][j][q] = 0.f;

    // ---------------- phase 1 ----------------
    cp_chunk(sb + OFF_B0, w1, 0, tid);
    CP_COMMIT();

    for (int c = 0; c < CH1; ++c) {
        { // gather A chunk -> A1 hi/lo (fp16 split)
            const int r = tid >> 1, half = tid & 1, rg = rowBase + r;
#pragma unroll
            for (int i = 0; i < 4; i++) {
                int kk = half * 16 + i * 4;
                int k = c * 32 + kk;
                float4 v = make_float4(0.f, 0.f, 0.f, 0.f);
                if (GATE) {
                    if (c < 4) v = *(const float4*)&emb[(long long)rg * EMB + k];
                    else if (c < 12) {
                        int s = axseg[r];
                        v = *(const float4*)&g_ctx[(long long)s * CTX + (k - 128)];
                    } else if (kk == 0) v.x = frac[rg];
                } else {
                    if (rg < M_SEG) {
                        float inv = axinv[r];
                        if (c < 4) {
                            v = *(const float4*)&g_pooled[(long long)rg * PSTR + k];
                            v.x *= inv; v.y *= inv; v.z *= inv; v.w *= inv;
                        } else if (kk == 0) {
                            v.x = g_pooled[(long long)rg * PSTR + 128] * inv;
                        }
                    }
                }
                uint32_t h01, l01, h23, l23;
                split2(v.x, v.y, h01, l01);
                split2(v.z, v.w, h23, l23);
                uint32_t off = (uint32_t)r * 80 + (uint32_t)kk * 2;
                STSV2(sb + OFF_A1 + off, h01, h23);
                STSV2(sb + OFF_A1 + 10240 + off, l01, l23);
            }
        }
        uint32_t curB = (c & 1) ? OFF_B1B : OFF_B0;
        if (c + 1 < CH1) {
            uint32_t nxtB = ((c + 1) & 1) ? OFF_B1B : OFF_B0;
            cp_chunk(sb + nxtB, w1, c + 1, tid);
            CP_COMMIT();
            CP_WAIT1();
        } else CP_WAIT0();
        __syncthreads();
        mma_chunk(acc, sb + OFF_A1, sb + OFF_A1 + 10240, 80,
                  sb + curB, lane, m0, n0w);
        __syncthreads();
    }

    // prefetch phase-2 chunk 0 early
    cp_chunk(sb + OFF_B20, w2, 0, tid);
    CP_COMMIT();

    // ---------------- epilogue 1: acc -> softplus -> A2 hi/lo ----------------
    {
        const int rb = m0 + (lane >> 2);
        const int cb = n0w + (lane & 3) * 2;
#pragma unroll
        for (int mi = 0; mi < 2; mi++)
#pragma unroll
            for (int ni = 0; ni < 16; ni++) {
                int col = cb + ni * 8;
                float2 bb = *(float2*)&bias1s[col];
                int row = rb + mi * 16;
                uint32_t ad = sb + OFF_A2 + (uint32_t)row * 528 + (uint32_t)col * 2;
                uint32_t hp, lp;
                float y0 = sp(acc[mi][ni][0] + bb.x), y1 = sp(acc[mi][ni][1] + bb.y);
                split2(y0, y1, hp, lp);
                STS32(ad, hp); STS32(ad + A2_HL, lp);
                float y2 = sp(acc[mi][ni][2] + bb.x), y3 = sp(acc[mi][ni][3] + bb.y);
                split2(y2, y3, hp, lp);
                STS32(ad + 8 * 528, hp); STS32(ad + 8 * 528 + A2_HL, lp);
                acc[mi][ni][0] = acc[mi][ni][1] = acc[mi][ni][2] = acc[mi][ni][3] = 0.f;
            }
    }

    // ---------------- phase 2 ----------------
    for (int c = 0; c < CH2; ++c) {
        uint32_t curB = (c & 1) ? OFF_B21 : OFF_B20;
        if (c + 1 < CH2) {
            uint32_t nxtB = ((c + 1) & 1) ? OFF_B21 : OFF_B20;
            cp_chunk(sb + nxtB, w2, c + 1, tid);
            CP_COMMIT();
            CP_WAIT1();
        } else CP_WAIT0();
        __syncthreads();
        // A base advances by c*32 K-columns (c*64 bytes)
        mma_chunk(acc, sb + OFF_A2 + (uint32_t)c * 64,
                  sb + OFF_A2 + A2_HL + (uint32_t)c * 64, 528,
                  sb + curB, lane, m0, n0w);
        __syncthreads();
    }

    // ---------------- epilogue 2: acc -> softplus -> out ----------------
    {
        float* dst = GATE ? outp : g_ctx;
        const int rb = m0 + (lane >> 2);
        const int cb = n0w + (lane & 3) * 2;
#pragma unroll
        for (int mi = 0; mi < 2; mi++)
#pragma unroll
            for (int ni = 0; ni < 16; ni++) {
                int col = cb + ni * 8;
                float2 bb = *(float2*)&bias2s[col];
                int row = rb + mi * 16;
                int gr = rowBase + row;
                float y0 = sp(acc[mi][ni][0] + bb.x), y1 = sp(acc[mi][ni][1] + bb.y);
                if (GATE || gr < M_SEG)
                    *(float2*)&dst[(long long)gr * 256 + col] = make_float2(y0, y1);
                float y2 = sp(acc[mi][ni][2] + bb.x), y3 = sp(acc[mi][ni][3] + bb.y);
                if (GATE || gr + 8 < M_SEG)
                    *(float2*)&dst[(long long)(gr + 8) * 256 + col] = make_float2(y2, y3);
            }
    }
}

// ---------------------------------------------------------------------------
extern "C" void kernel_launch(void* const* d_in, const int* in_sizes, int n_in,
                              void* d_out, int out_size) {
    const float* emb  = (const float*)d_in[0];
    const float* frac = (const float*)d_in[1];
    const int*   seg  = (const int*)  d_in[2];
    const float* iW1  = (const float*)d_in[3];
    const float* ib1  = (const float*)d_in[4];
    const float* iW2  = (const float*)d_in[5];
    const float* ib2  = (const float*)d_in[6];
    const float* gW1  = (const float*)d_in[7];
    const float* gb1  = (const float*)d_in[8];
    const float* gW2  = (const float*)d_in[9];
    const float* gb2  = (const float*)d_in[10];
    float* out = (float*)d_out;

    cudaFuncSetAttribute(k_mlp<0>, cudaFuncAttributeMaxDynamicSharedMemorySize, SMEM_TOTAL);
    cudaFuncSetAttribute(k_mlp<1>, cudaFuncAttributeMaxDynamicSharedMemorySize, SMEM_TOTAL);

    k_prep<<<(13*10240 + 255)/256, 256>>>(gW1, 1, 13, 385, 0);
    k_prep<<<(8*10240  + 255)/256, 256>>>(gW2, 0, 8, 256, 1);
    k_prep<<<(5*10240  + 255)/256, 256>>>(iW1, 0, 5, 129, 2);
    k_prep<<<(8*10240  + 255)/256, 256>>>(iW2, 0, 8, 256, 3);

    long long totz = (long long)M_SEG * PSTR + M_SEG;
    k_zero<<<(unsigned)((totz + 255)/256), 256>>>();

    float* out_frac = nullptr;
    if ((long long)out_size >= (long long)N_ROWS * (LAT + 1))
        out_frac = out + (size_t)N_ROWS * LAT;
    long long tota = (long long)N_ROWS * 33;
    k_accum<<<(unsigned)((tota + 255)/256), 256>>>(emb, frac, seg, out_frac);

    k_mlp<0><<<(M_SEG + 127)/128, 256, SMEM_TOTAL>>>(emb, frac, seg, ib1, ib2, nullptr);
    k_mlp<1><<<N_ROWS / 128, 256, SMEM_TOTAL>>>(emb, frac, seg, gb1, gb2, out);
}

// round 7
// speedup vs baseline: 4.0734x; 1.3272x over previous
#include <cuda_runtime.h>
#include <cuda_fp16.h>
#include <cstdint>
#include <math.h>

#define N_ROWS 400000
#define M_SEG  100000
#define EMB    128
#define CTX    256
#define LAT    256
#define K_MIX  129
#define PSTR   132

// smem layout (bytes)
#define OFF_B1S   0        // bias1: 256 f32
#define OFF_B2S   1024     // bias2: 256 f32
#define OFF_AUX   2048     // 128 ints/floats
#define OFF_A1    4096     // A1: 128 x 80B = 10240 -> 14336
#define OFF_A2    4096     // A2: 128 x 528B = 67584 -> 71680 (phase 2)
#define OFF_B0    71680    // B buf0: 20480 -> 92160
#define OFF_B1B   92160    // B buf1: 20480 -> 112640
#define SMEM_TOTAL 112640

// scratch globals
__device__ float g_pooled[(size_t)M_SEG * PSTR];
__device__ float g_counts[M_SEG];
__device__ float g_ctx[(size_t)M_SEG * CTX];
// prepped B chunk images: [chunk][256][40] fp16 (RN)
__device__ __align__(16) __half g_gw1[13*10240];
__device__ __align__(16) __half g_gw2[8*10240];
__device__ __align__(16) __half g_mw1[5*10240];
__device__ __align__(16) __half g_mw2[8*10240];

__device__ __forceinline__ uint32_t smem_u32(const void* p) {
    uint32_t a;
    asm("{ .reg .u64 t; cvta.to.shared.u64 t, %1; cvt.u32.u64 %0, t; }" : "=r"(a) : "l"(p));
    return a;
}
#define LDSM4(r0,r1,r2,r3,addr) \
    asm volatile("ldmatrix.sync.aligned.m8n8.x4.shared.b16 {%0,%1,%2,%3}, [%4];" \
        : "=r"(r0),"=r"(r1),"=r"(r2),"=r"(r3) : "r"(addr))
#define MMA(d,a,b0,b1) \
    asm volatile("mma.sync.aligned.m16n8k16.row.col.f32.f16.f16.f32 " \
        "{%0,%1,%2,%3},{%4,%5,%6,%7},{%8,%9},{%0,%1,%2,%3};" \
        : "+f"((d)[0]),"+f"((d)[1]),"+f"((d)[2]),"+f"((d)[3]) \
        : "r"((a)[0]),"r"((a)[1]),"r"((a)[2]),"r"((a)[3]),"r"(b0),"r"(b1))
#define CP16(sa,gp) asm volatile("cp.async.cg.shared.global [%0], [%1], 16;" :: "r"(sa),"l"(gp))
#define CP_COMMIT() asm volatile("cp.async.commit_group;" ::: "memory")
#define CP_WAIT0()  asm volatile("cp.async.wait_group 0;" ::: "memory")
#define CP_WAIT1()  asm volatile("cp.async.wait_group 1;" ::: "memory")
#define STS32(a,v)  asm volatile("st.shared.b32 [%0], %1;" :: "r"(a),"r"(v) : "memory")
#define STSV2(a,x,y) asm volatile("st.shared.v2.b32 [%0], {%1,%2};" :: "r"(a),"r"(x),"r"(y) : "memory")
#define REDV4(p,v) \
    asm volatile("red.global.add.v4.f32 [%0], {%1,%2,%3,%4};" \
        :: "l"(p), "f"((v).x), "f"((v).y), "f"((v).z), "f"((v).w) : "memory")

__device__ __forceinline__ float sp(float x) {
    return fmaxf(x, 0.f) + __logf(1.f + __expf(-fabsf(x)));
}
__device__ __forceinline__ uint32_t pack2h(float a, float b) {
    __half2 h = __floats2half2_rn(a, b);
    return *(uint32_t*)&h;
}

// ---------------------------------------------------------------------------
__global__ void k_zero() {
    long long i = (long long)blockIdx.x * 256 + threadIdx.x;
    const long long P = (long long)M_SEG * PSTR;
    if (i < P) g_pooled[i] = 0.f;
    else if (i < P + M_SEG) g_counts[i - P] = 0.f;
}

// one thread per (row, float4-group); group 32 = frac + count
__global__ void k_accum(const float* __restrict__ emb, const float* __restrict__ frac,
                        const int* __restrict__ seg, float* __restrict__ out_frac) {
    int idx = blockIdx.x * 256 + threadIdx.x;
    if (idx >= N_ROWS * 33) return;
    int r = idx / 33;
    int g = idx - r * 33;
    int s = seg[r];
    if (g < 32) {
        float4 v = *(const float4*)&emb[(long long)r * EMB + g * 4];
        REDV4(&g_pooled[(long long)s * PSTR + g * 4], v);
    } else {
        float f = frac[r];
        atomicAdd(&g_pooled[(long long)s * PSTR + 128], f);
        atomicAdd(&g_counts[s], 1.f);
        if (out_frac) out_frac[r] = f;
    }
}

// prep: W[Ksrc][256] -> chunk images [c][n][kk] fp16 RN (kk pad 40, zero)
__global__ void k_prep(const float* __restrict__ W, int mode, int nch, int Kreal, int which) {
    __half* dh;
    if (which == 0)      dh = g_gw1;
    else if (which == 1) dh = g_gw2;
    else if (which == 2) dh = g_mw1;
    else                 dh = g_mw2;
    int idx = blockIdx.x * 256 + threadIdx.x;
    if (idx >= nch * 10240) return;
    int c = idx / 10240, rem = idx - c * 10240;
    int n = rem / 40, kk = rem - n * 40;
    float v = 0.f;
    if (kk < 32) {
        int kg = c * 32 + kk, sr;
        if (mode == 1) sr = kg < 128 ? kg : (kg < 384 ? kg + 1 : (kg == 384 ? 128 : -1));
        else           sr = (kg < Kreal) ? kg : -1;
        if (sr >= 0) v = W[(long long)sr * 256 + n];
    }
    dh[idx] = __float2half_rn(v);
}

// ---------------------------------------------------------------------------
__device__ __forceinline__ void cp_chunk(uint32_t dst, const __half* src, int c, int tid) {
    const uint4* gp = (const uint4*)src + (long long)c * 1280;
#pragma unroll
    for (int j = 0; j < 5; j++) {
        int i = tid + j * 256;
        CP16(dst + i * 16, gp + i);
    }
}

// single-pass fp16 MMA over one 32-wide K chunk; warp tile 32x128
__device__ __forceinline__ void mma_chunk(float (&acc)[2][16][4],
                                          uint32_t aBase, int aStride,
                                          uint32_t bBase,
                                          int lane, int m0, int n0w) {
    const int arow = (lane & 7) + ((lane >> 3) & 1) * 8;
    const int brow = (lane & 7) + (lane >> 4) * 8;
    const int bk0  = ((lane >> 3) & 1) * 16;
#pragma unroll
    for (int ks = 0; ks < 2; ks++) {
        uint32_t ah[2][4];
        int akb = ks * 32 + (lane >> 4) * 16;
#pragma unroll
        for (int mi = 0; mi < 2; mi++) {
            uint32_t ra = aBase + (uint32_t)(m0 + mi * 16 + arow) * aStride + akb;
            LDSM4(ah[mi][0], ah[mi][1], ah[mi][2], ah[mi][3], ra);
        }
        int bkb = ks * 32 + bk0;
#pragma unroll
        for (int g = 0; g < 8; g++) {
            uint32_t bh[4];
            uint32_t ro = (uint32_t)(n0w + g * 16 + brow) * 80 + bkb;
            LDSM4(bh[0], bh[1], bh[2], bh[3], bBase + ro);
#pragma unroll
            for (int mi = 0; mi < 2; mi++) {
                MMA(acc[mi][2*g],   ah[mi], bh[0], bh[1]);
                MMA(acc[mi][2*g+1], ah[mi], bh[2], bh[3]);
            }
        }
    }
}

template<int GATE>
__global__ __launch_bounds__(256, 1)
void k_mlp(const float* __restrict__ emb, const float* __restrict__ frac,
           const int* __restrict__ seg,
           const float* __restrict__ b1v, const float* __restrict__ b2v,
           float* __restrict__ outp) {
    extern __shared__ __align__(16) char sm[];
    const uint32_t sb = smem_u32(sm);
    const int tid = threadIdx.x, w = tid >> 5, lane = tid & 31;
    const int m0 = (w & 3) * 32, n0w = (w >> 2) * 128;
    const int rowBase = blockIdx.x * 128;
    constexpr int CH1 = GATE ? 13 : 5;   // both odd (phase-2 parity flips)
    constexpr int CH2 = 8;

    float* bias1s = (float*)(sm + OFF_B1S);
    float* bias2s = (float*)(sm + OFF_B2S);
    int*   axseg  = (int*)  (sm + OFF_AUX);
    float* axinv  = (float*)(sm + OFF_AUX);

    bias1s[tid] = b1v[tid];
    bias2s[tid] = b2v[tid];
    if (tid < 128) {
        if (GATE) axseg[tid] = seg[rowBase + tid];
        else {
            int gr = rowBase + tid;
            float c = (gr < M_SEG) ? g_counts[gr] : 1.f;
            axinv[tid] = 1.f / fmaxf(c, 1.f);
        }
    }
    __syncthreads();

    const __half* w1 = GATE ? g_gw1 : g_mw1;
    const __half* w2 = GATE ? g_gw2 : g_mw2;

    float acc[2][16][4];
#pragma unroll
    for (int i = 0; i < 2; i++)
#pragma unroll
        for (int j = 0; j < 16; j++)
#pragma unroll
            for (int q = 0; q < 4; q++) acc[i][j][q] = 0.f;

    // ---------------- phase 1 ----------------
    cp_chunk(sb + OFF_B0, w1, 0, tid);
    CP_COMMIT();

    for (int c = 0; c < CH1; ++c) {
        { // gather A chunk -> A1 (fp16 RN)
            const int r = tid >> 1, half = tid & 1, rg = rowBase + r;
#pragma unroll
            for (int i = 0; i < 4; i++) {
                int kk = half * 16 + i * 4;
                int k = c * 32 + kk;
                float4 v = make_float4(0.f, 0.f, 0.f, 0.f);
                if (GATE) {
                    if (c < 4) v = *(const float4*)&emb[(long long)rg * EMB + k];
                    else if (c < 12) {
                        int s = axseg[r];
                        v = *(const float4*)&g_ctx[(long long)s * CTX + (k - 128)];
                    } else if (kk == 0) v.x = frac[rg];
                } else {
                    if (rg < M_SEG) {
                        float inv = axinv[r];
                        if (c < 4) {
                            v = *(const float4*)&g_pooled[(long long)rg * PSTR + k];
                            v.x *= inv; v.y *= inv; v.z *= inv; v.w *= inv;
                        } else if (kk == 0) {
                            v.x = g_pooled[(long long)rg * PSTR + 128] * inv;
                        }
                    }
                }
                uint32_t off = (uint32_t)r * 80 + (uint32_t)kk * 2;
                STSV2(sb + OFF_A1 + off, pack2h(v.x, v.y), pack2h(v.z, v.w));
            }
        }
        uint32_t curB = (c & 1) ? OFF_B1B : OFF_B0;
        if (c + 1 < CH1) {
            uint32_t nxtB = ((c + 1) & 1) ? OFF_B1B : OFF_B0;
            cp_chunk(sb + nxtB, w1, c + 1, tid);
            CP_COMMIT();
            CP_WAIT1();
        } else CP_WAIT0();
        __syncthreads();
        mma_chunk(acc, sb + OFF_A1, 80, sb + curB, lane, m0, n0w);
        __syncthreads();
    }

    // prefetch phase-2 chunk 0 (into the buffer NOT used by last phase-1 chunk)
    cp_chunk(sb + OFF_B1B, w2, 0, tid);   // CH1 odd -> last used OFF_B0
    CP_COMMIT();

    // ---------------- epilogue 1: acc -> softplus -> A2 fp16 ----------------
    {
        const int rb = m0 + (lane >> 2);
        const int cb = n0w + (lane & 3) * 2;
#pragma unroll
        for (int mi = 0; mi < 2; mi++)
#pragma unroll
            for (int ni = 0; ni < 16; ni++) {
                int col = cb + ni * 8;
                float2 bb = *(float2*)&bias1s[col];
                int row = rb + mi * 16;
                uint32_t ad = sb + OFF_A2 + (uint32_t)row * 528 + (uint32_t)col * 2;
                float y0 = sp(acc[mi][ni][0] + bb.x), y1 = sp(acc[mi][ni][1] + bb.y);
                STS32(ad, pack2h(y0, y1));
                float y2 = sp(acc[mi][ni][2] + bb.x), y3 = sp(acc[mi][ni][3] + bb.y);
                STS32(ad + 8 * 528, pack2h(y2, y3));
                acc[mi][ni][0] = acc[mi][ni][1] = acc[mi][ni][2] = acc[mi][ni][3] = 0.f;
            }
    }

    // ---------------- phase 2 ----------------
    for (int c = 0; c < CH2; ++c) {
        uint32_t curB = (c & 1) ? OFF_B0 : OFF_B1B;   // parity continues from phase 1
        if (c + 1 < CH2) {
            uint32_t nxtB = ((c + 1) & 1) ? OFF_B0 : OFF_B1B;
            cp_chunk(sb + nxtB, w2, c + 1, tid);
            CP_COMMIT();
            CP_WAIT1();
        } else CP_WAIT0();
        __syncthreads();
        // A base advances by c*32 K-columns (c*64 bytes)
        mma_chunk(acc, sb + OFF_A2 + (uint32_t)c * 64, 528,
                  sb + curB, lane, m0, n0w);
        __syncthreads();
    }

    // ---------------- epilogue 2: acc -> softplus -> out ----------------
    {
        float* dst = GATE ? outp : g_ctx;
        const int rb = m0 + (lane >> 2);
        const int cb = n0w + (lane & 3) * 2;
#pragma unroll
        for (int mi = 0; mi < 2; mi++)
#pragma unroll
            for (int ni = 0; ni < 16; ni++) {
                int col = cb + ni * 8;
                float2 bb = *(float2*)&bias2s[col];
                int row = rb + mi * 16;
                int gr = rowBase + row;
                float y0 = sp(acc[mi][ni][0] + bb.x), y1 = sp(acc[mi][ni][1] + bb.y);
                if (GATE || gr < M_SEG)
                    *(float2*)&dst[(long long)gr * 256 + col] = make_float2(y0, y1);
                float y2 = sp(acc[mi][ni][2] + bb.x), y3 = sp(acc[mi][ni][3] + bb.y);
                if (GATE || gr + 8 < M_SEG)
                    *(float2*)&dst[(long long)(gr + 8) * 256 + col] = make_float2(y2, y3);
            }
    }
}

// ---------------------------------------------------------------------------
extern "C" void kernel_launch(void* const* d_in, const int* in_sizes, int n_in,
                              void* d_out, int out_size) {
    const float* emb  = (const float*)d_in[0];
    const float* frac = (const float*)d_in[1];
    const int*   seg  = (const int*)  d_in[2];
    const float* iW1  = (const float*)d_in[3];
    const float* ib1  = (const float*)d_in[4];
    const float* iW2  = (const float*)d_in[5];
    const float* ib2  = (const float*)d_in[6];
    const float* gW1  = (const float*)d_in[7];
    const float* gb1  = (const float*)d_in[8];
    const float* gW2  = (const float*)d_in[9];
    const float* gb2  = (const float*)d_in[10];
    float* out = (float*)d_out;

    cudaFuncSetAttribute(k_mlp<0>, cudaFuncAttributeMaxDynamicSharedMemorySize, SMEM_TOTAL);
    cudaFuncSetAttribute(k_mlp<1>, cudaFuncAttributeMaxDynamicSharedMemorySize, SMEM_TOTAL);

    k_prep<<<(13*10240 + 255)/256, 256>>>(gW1, 1, 13, 385, 0);
    k_prep<<<(8*10240  + 255)/256, 256>>>(gW2, 0, 8, 256, 1);
    k_prep<<<(5*10240  + 255)/256, 256>>>(iW1, 0, 5, 129, 2);
    k_prep<<<(8*10240  + 255)/256, 256>>>(iW2, 0, 8, 256, 3);

    long long totz = (long long)M_SEG * PSTR + M_SEG;
    k_zero<<<(unsigned)((totz + 255)/256), 256>>>();

    float* out_frac = nullptr;
    if ((long long)out_size >= (long long)N_ROWS * (LAT + 1))
        out_frac = out + (size_t)N_ROWS * LAT;
    long long tota = (long long)N_ROWS * 33;
    k_accum<<<(unsigned)((tota + 255)/256), 256>>>(emb, frac, seg, out_frac);

    k_mlp<0><<<(M_SEG + 127)/128, 256, SMEM_TOTAL>>>(emb, frac, seg, ib1, ib2, nullptr);
    k_mlp<1><<<N_ROWS / 128, 256, SMEM_TOTAL>>>(emb, frac, seg, gb1, gb2, out);
}

// round 8
// speedup vs baseline: 4.9853x; 1.2239x over previous
#include <cuda_runtime.h>
#include <cuda_fp16.h>
#include <cstdint>
#include <math.h>

#define N_ROWS 400000
#define M_SEG  100000
#define EMB    128
#define CTX    256
#define LAT    256
#define PSTR   132

// smem layout (bytes)
#define OFF_B1S   0          // bias1: 256 f32
#define OFF_B2S   1024       // bias2: 256 f32
#define OFF_AUX   2048       // 128 ints/floats
#define OFF_A2    4096       // A2: 128 x 528B = 67584 -> 71680 (phase 2)
#define OFF_A10   4096       // A1 buf0 (phase 1, aliases A2 region): 18432
#define OFF_A11   22528      // A1 buf1: 18432 -> 40960
#define OFF_BB0   71680      // B buf0: 36864 -> 108544
#define OFF_BB1   108544     // B buf1: 36864 -> 145408
#define SMEM_TOTAL 145408

#define CHW 18432            // halves per 64-wide B chunk image (256 x 72)

// scratch globals
__device__ float g_pooled[(size_t)M_SEG * PSTR];
__device__ float g_counts[M_SEG];
__device__ float g_ctx[(size_t)M_SEG * CTX];
// prepped B chunk images: [chunk][256][72] fp16 (RN), 64 K-cols + 8 pad
__device__ __align__(16) __half g_gw1[7*CHW];
__device__ __align__(16) __half g_gw2[4*CHW];
__device__ __align__(16) __half g_mw1[3*CHW];
__device__ __align__(16) __half g_mw2[4*CHW];

__device__ __forceinline__ uint32_t smem_u32(const void* p) {
    uint32_t a;
    asm("{ .reg .u64 t; cvta.to.shared.u64 t, %1; cvt.u32.u64 %0, t; }" : "=r"(a) : "l"(p));
    return a;
}
#define LDSM4(r0,r1,r2,r3,addr) \
    asm volatile("ldmatrix.sync.aligned.m8n8.x4.shared.b16 {%0,%1,%2,%3}, [%4];" \
        : "=r"(r0),"=r"(r1),"=r"(r2),"=r"(r3) : "r"(addr))
#define MMA(d,a,b0,b1) \
    asm volatile("mma.sync.aligned.m16n8k16.row.col.f32.f16.f16.f32 " \
        "{%0,%1,%2,%3},{%4,%5,%6,%7},{%8,%9},{%0,%1,%2,%3};" \
        : "+f"((d)[0]),"+f"((d)[1]),"+f"((d)[2]),"+f"((d)[3]) \
        : "r"((a)[0]),"r"((a)[1]),"r"((a)[2]),"r"((a)[3]),"r"(b0),"r"(b1))
#define CP16(sa,gp) asm volatile("cp.async.cg.shared.global [%0], [%1], 16;" :: "r"(sa),"l"(gp))
#define CP_COMMIT() asm volatile("cp.async.commit_group;" ::: "memory")
#define CP_WAIT0()  asm volatile("cp.async.wait_group 0;" ::: "memory")
#define STS32(a,v)  asm volatile("st.shared.b32 [%0], %1;" :: "r"(a),"r"(v) : "memory")
#define STSV2(a,x,y) asm volatile("st.shared.v2.b32 [%0], {%1,%2};" :: "r"(a),"r"(x),"r"(y) : "memory")
#define REDV4(p,v) \
    asm volatile("red.global.add.v4.f32 [%0], {%1,%2,%3,%4};" \
        :: "l"(p), "f"((v).x), "f"((v).y), "f"((v).z), "f"((v).w) : "memory")

__device__ __forceinline__ float sp(float x) {
    return fmaxf(x, 0.f) + __logf(1.f + __expf(-fabsf(x)));
}
__device__ __forceinline__ uint32_t pack2h(float a, float b) {
    __half2 h = __floats2half2_rn(a, b);
    return *(uint32_t*)&h;
}

// ---------------------------------------------------------------------------
__global__ void k_zero() {
    long long i = (long long)blockIdx.x * 256 + threadIdx.x;
    const long long P = (long long)M_SEG * PSTR;
    if (i < P) g_pooled[i] = 0.f;
    else if (i < P + M_SEG) g_counts[i - P] = 0.f;
}

__global__ void k_accum(const float* __restrict__ emb, const float* __restrict__ frac,
                        const int* __restrict__ seg, float* __restrict__ out_frac) {
    int idx = blockIdx.x * 256 + threadIdx.x;
    if (idx >= N_ROWS * 33) return;
    int r = idx / 33;
    int g = idx - r * 33;
    int s = seg[r];
    if (g < 32) {
        float4 v = *(const float4*)&emb[(long long)r * EMB + g * 4];
        REDV4(&g_pooled[(long long)s * PSTR + g * 4], v);
    } else {
        float f = frac[r];
        atomicAdd(&g_pooled[(long long)s * PSTR + 128], f);
        atomicAdd(&g_counts[s], 1.f);
        if (out_frac) out_frac[r] = f;
    }
}

// prep: W[Ksrc][256] -> chunk images [c][n][kk] fp16 RN (kk = 64 data + 8 pad)
__global__ void k_prep(const float* __restrict__ W, int mode, int nch, int Kreal, int which) {
    __half* dh;
    if (which == 0)      dh = g_gw1;
    else if (which == 1) dh = g_gw2;
    else if (which == 2) dh = g_mw1;
    else                 dh = g_mw2;
    int idx = blockIdx.x * 256 + threadIdx.x;
    if (idx >= nch * CHW) return;
    int c = idx / CHW, rem = idx - c * CHW;
    int n = rem / 72, kk = rem - n * 72;
    float v = 0.f;
    if (kk < 64) {
        int kg = c * 64 + kk, sr;
        if (mode == 1) sr = kg < 128 ? kg : (kg < 384 ? kg + 1 : (kg == 384 ? 128 : -1));
        else           sr = (kg < Kreal) ? kg : -1;
        if (sr >= 0) v = W[(long long)sr * 256 + n];
    }
    dh[idx] = __float2half_rn(v);
}

// ---------------------------------------------------------------------------
__device__ __forceinline__ void cp_chunk(uint32_t dst, const __half* src, int c, int tid) {
    const uint4* gp = (const uint4*)src + (long long)c * (CHW / 8);
#pragma unroll
    for (int j = 0; j < 9; j++) {
        int i = tid + j * 256;
        CP16(dst + i * 16, gp + i);
    }
}

// fp16 MMA over one 64-wide K chunk; warp tile 32x128; B stride 144B
__device__ __forceinline__ void mma_chunk(float (&acc)[2][16][4],
                                          uint32_t aBase, int aStride,
                                          uint32_t bBase,
                                          int lane, int m0, int n0w) {
    const int arow = (lane & 7) + ((lane >> 3) & 1) * 8;
    const int brow = (lane & 7) + (lane >> 4) * 8;
    const int bk0  = ((lane >> 3) & 1) * 16;
#pragma unroll
    for (int ks = 0; ks < 4; ks++) {
        uint32_t ah[2][4];
        int akb = ks * 32 + (lane >> 4) * 16;
#pragma unroll
        for (int mi = 0; mi < 2; mi++) {
            uint32_t ra = aBase + (uint32_t)(m0 + mi * 16 + arow) * aStride + akb;
            LDSM4(ah[mi][0], ah[mi][1], ah[mi][2], ah[mi][3], ra);
        }
        int bkb = ks * 32 + bk0;
#pragma unroll
        for (int g = 0; g < 8; g++) {
            uint32_t bh[4];
            uint32_t ro = (uint32_t)(n0w + g * 16 + brow) * 144 + bkb;
            LDSM4(bh[0], bh[1], bh[2], bh[3], bBase + ro);
#pragma unroll
            for (int mi = 0; mi < 2; mi++) {
                MMA(acc[mi][2*g],   ah[mi], bh[0], bh[1]);
                MMA(acc[mi][2*g+1], ah[mi], bh[2], bh[3]);
            }
        }
    }
}

template<int GATE>
__global__ __launch_bounds__(256, 1)
void k_mlp(const float* __restrict__ emb, const float* __restrict__ frac,
           const int* __restrict__ seg,
           const float* __restrict__ b1v, const float* __restrict__ b2v,
           float* __restrict__ outp) {
    extern __shared__ __align__(16) char sm[];
    const uint32_t sb = smem_u32(sm);
    const int tid = threadIdx.x, w = tid >> 5, lane = tid & 31;
    const int m0 = (w & 3) * 32, n0w = (w >> 2) * 128;
    const int rowBase = blockIdx.x * 128;
    constexpr int CH1 = GATE ? 7 : 3;   // both odd
    constexpr int CH2 = 4;

    float* bias1s = (float*)(sm + OFF_B1S);
    float* bias2s = (float*)(sm + OFF_B2S);
    int*   axseg  = (int*)  (sm + OFF_AUX);
    float* axinv  = (float*)(sm + OFF_AUX);

    bias1s[tid] = b1v[tid];
    bias2s[tid] = b2v[tid];
    if (tid < 128) {
        if (GATE) axseg[tid] = seg[rowBase + tid];
        else {
            int gr = rowBase + tid;
            float c = (gr < M_SEG) ? g_counts[gr] : 1.f;
            axinv[tid] = 1.f / fmaxf(c, 1.f);
        }
    }
    __syncthreads();   // axseg/axinv visible for gathers

    const __half* w1 = GATE ? g_gw1 : g_mw1;
    const __half* w2 = GATE ? g_gw2 : g_mw2;

    // gather one 64-wide A chunk into 16 packed-half2 regs
    const int gr_ = tid >> 1, ghalf = tid & 1;
    const int rg = rowBase + gr_;
    const int kk0 = ghalf * 32;
    auto gather = [&](int c, uint32_t (&ar)[16]) {
#pragma unroll
        for (int i = 0; i < 8; i++) {
            int kk = kk0 + i * 4;
            int k = c * 64 + kk;
            float4 v = make_float4(0.f, 0.f, 0.f, 0.f);
            if (GATE) {
                if (c < 2) v = *(const float4*)&emb[(long long)rg * EMB + k];
                else if (c < 6) {
                    int s = axseg[gr_];
                    v = *(const float4*)&g_ctx[(long long)s * CTX + (k - 128)];
                } else if (kk == 0) v.x = frac[rg];
            } else {
                if (rg < M_SEG) {
                    float inv = axinv[gr_];
                    if (c < 2) {
                        v = *(const float4*)&g_pooled[(long long)rg * PSTR + k];
                        v.x *= inv; v.y *= inv; v.z *= inv; v.w *= inv;
                    } else if (kk == 0) {
                        v.x = g_pooled[(long long)rg * PSTR + 128] * inv;
                    }
                }
            }
            ar[2*i]   = pack2h(v.x, v.y);
            ar[2*i+1] = pack2h(v.z, v.w);
        }
    };
    auto stsA = [&](uint32_t abuf, const uint32_t (&ar)[16]) {
        uint32_t base = abuf + (uint32_t)gr_ * 144 + (uint32_t)kk0 * 2;
#pragma unroll
        for (int i = 0; i < 8; i++)
            STSV2(base + i * 8, ar[2*i], ar[2*i+1]);
    };

    float acc[2][16][4];
#pragma unroll
    for (int i = 0; i < 2; i++)
#pragma unroll
        for (int j = 0; j < 16; j++)
#pragma unroll
            for (int q = 0; q < 4; q++) acc[i][j][q] = 0.f;

    // ---------------- phase 1: 1 sync per chunk, A+B double-buffered --------
    {
        uint32_t ar[16];
        gather(0, ar);
        stsA(sb + OFF_A10, ar);
        cp_chunk(sb + OFF_BB0, w1, 0, tid);
        CP_COMMIT();
    }
    for (int c = 0; c < CH1; ++c) {
        uint32_t ar[16];
        if (c + 1 < CH1) gather(c + 1, ar);           // LDGs in flight
        CP_WAIT0();                                   // B[c] arrived
        __syncthreads();                              // A[c] STS + B[c] visible
        if (c + 1 < CH1) {
            cp_chunk(sb + (((c + 1) & 1) ? OFF_BB1 : OFF_BB0), w1, c + 1, tid);
            CP_COMMIT();
        }
        mma_chunk(acc, sb + ((c & 1) ? OFF_A11 : OFF_A10), 144,
                  sb + ((c & 1) ? OFF_BB1 : OFF_BB0), lane, m0, n0w);
        if (c + 1 < CH1) stsA(sb + (((c + 1) & 1) ? OFF_A11 : OFF_A10), ar);
    }
    __syncthreads();   // all mma done before A2 overwrites A1 region

    // prefetch phase-2 chunk 0 (CH1 odd -> last B buf used was BB0)
    cp_chunk(sb + OFF_BB1, w2, 0, tid);
    CP_COMMIT();

    // ---------------- epilogue 1: acc -> softplus -> A2 fp16 ----------------
    {
        const int rb = m0 + (lane >> 2);
        const int cb = n0w + (lane & 3) * 2;
#pragma unroll
        for (int mi = 0; mi < 2; mi++)
#pragma unroll
            for (int ni = 0; ni < 16; ni++) {
                int col = cb + ni * 8;
                float2 bb = *(float2*)&bias1s[col];
                int row = rb + mi * 16;
                uint32_t ad = sb + OFF_A2 + (uint32_t)row * 528 + (uint32_t)col * 2;
                float y0 = sp(acc[mi][ni][0] + bb.x), y1 = sp(acc[mi][ni][1] + bb.y);
                STS32(ad, pack2h(y0, y1));
                float y2 = sp(acc[mi][ni][2] + bb.x), y3 = sp(acc[mi][ni][3] + bb.y);
                STS32(ad + 8 * 528, pack2h(y2, y3));
                acc[mi][ni][0] = acc[mi][ni][1] = acc[mi][ni][2] = acc[mi][ni][3] = 0.f;
            }
    }

    // ---------------- phase 2: B double-buffered, parity continues ----------
    for (int c = 0; c < CH2; ++c) {
        CP_WAIT0();
        __syncthreads();   // iter0: epilogue-1 STS visible; iterN: B reuse safe
        if (c + 1 < CH2) {
            cp_chunk(sb + (((CH1 + c + 1) & 1) ? OFF_BB1 : OFF_BB0), w2, c + 1, tid);
            CP_COMMIT();
        }
        mma_chunk(acc, sb + OFF_A2 + (uint32_t)c * 128, 528,
                  sb + (((CH1 + c) & 1) ? OFF_BB1 : OFF_BB0), lane, m0, n0w);
    }

    // ---------------- epilogue 2: acc -> softplus -> out --------------------
    {
        float* dst = GATE ? outp : g_ctx;
        const int rb = m0 + (lane >> 2);
        const int cb = n0w + (lane & 3) * 2;
#pragma unroll
        for (int mi = 0; mi < 2; mi++)
#pragma unroll
            for (int ni = 0; ni < 16; ni++) {
                int col = cb + ni * 8;
                float2 bb = *(float2*)&bias2s[col];
                int row = rb + mi * 16;
                int gr = rowBase + row;
                float y0 = sp(acc[mi][ni][0] + bb.x), y1 = sp(acc[mi][ni][1] + bb.y);
                if (GATE || gr < M_SEG)
                    *(float2*)&dst[(long long)gr * 256 + col] = make_float2(y0, y1);
                float y2 = sp(acc[mi][ni][2] + bb.x), y3 = sp(acc[mi][ni][3] + bb.y);
                if (GATE || gr + 8 < M_SEG)
                    *(float2*)&dst[(long long)(gr + 8) * 256 + col] = make_float2(y2, y3);
            }
    }
}

// ---------------------------------------------------------------------------
extern "C" void kernel_launch(void* const* d_in, const int* in_sizes, int n_in,
                              void* d_out, int out_size) {
    const float* emb  = (const float*)d_in[0];
    const float* frac = (const float*)d_in[1];
    const int*   seg  = (const int*)  d_in[2];
    const float* iW1  = (const float*)d_in[3];
    const float* ib1  = (const float*)d_in[4];
    const float* iW2  = (const float*)d_in[5];
    const float* ib2  = (const float*)d_in[6];
    const float* gW1  = (const float*)d_in[7];
    const float* gb1  = (const float*)d_in[8];
    const float* gW2  = (const float*)d_in[9];
    const float* gb2  = (const float*)d_in[10];
    float* out = (float*)d_out;

    cudaFuncSetAttribute(k_mlp<0>, cudaFuncAttributeMaxDynamicSharedMemorySize, SMEM_TOTAL);
    cudaFuncSetAttribute(k_mlp<1>, cudaFuncAttributeMaxDynamicSharedMemorySize, SMEM_TOTAL);

    k_prep<<<(7*CHW + 255)/256, 256>>>(gW1, 1, 7, 385, 0);
    k_prep<<<(4*CHW + 255)/256, 256>>>(gW2, 0, 4, 256, 1);
    k_prep<<<(3*CHW + 255)/256, 256>>>(iW1, 0, 3, 129, 2);
    k_prep<<<(4*CHW + 255)/256, 256>>>(iW2, 0, 4, 256, 3);

    long long totz = (long long)M_SEG * PSTR + M_SEG;
    k_zero<<<(unsigned)((totz + 255)/256), 256>>>();

    float* out_frac = nullptr;
    if ((long long)out_size >= (long long)N_ROWS * (LAT + 1))
        out_frac = out + (size_t)N_ROWS * LAT;
    long long tota = (long long)N_ROWS * 33;
    k_accum<<<(unsigned)((tota + 255)/256), 256>>>(emb, frac, seg, out_frac);

    k_mlp<0><<<(M_SEG + 127)/128, 256, SMEM_TOTAL>>>(emb, frac, seg, ib1, ib2, nullptr);
    k_mlp<1><<<N_ROWS / 128, 256, SMEM_TOTAL>>>(emb, frac, seg, gb1, gb2, out);
}

// round 9
// speedup vs baseline: 5.2069x; 1.0445x over previous
#include <cuda_runtime.h>
#include <cuda_fp16.h>
#include <cstdint>
#include <math.h>

#define N_ROWS 400000
#define M_SEG  100000
#define EMB    128
#define CTX    256
#define LAT    256
#define PHSTR  136           // pooled row stride in halves (272B, 16B aligned)

// smem layout (bytes)
#define OFF_B1S   0          // bias1: 256 f32
#define OFF_B2S   1024       // bias2: 256 f32
#define OFF_AUX   2048       // 128 ints/floats
#define OFF_A2    4096       // A2: 128 x 528B = 67584 -> 71680 (phase 2)
#define OFF_A10   4096       // A1 buf0 (phase 1, aliases A2 region)
#define OFF_A11   22528      // A1 buf1
#define OFF_BB0   71680      // B buf0: 36864 -> 108544
#define OFF_BB1   108544     // B buf1: 36864 -> 145408
#define SMEM_TOTAL 145408

#define CHW 18432            // halves per 64-wide B chunk image (256 x 72)

// scratch globals
__device__ __align__(16) __half g_pooled[(size_t)M_SEG * PHSTR];  // fp16 segment sums
__device__ float g_counts[M_SEG];
__device__ float g_ctx[(size_t)M_SEG * CTX];
// prepped B chunk images: [chunk][256][72] fp16 (RN), 64 K-cols + 8 pad
__device__ __align__(16) __half g_gw1[7*CHW];
__device__ __align__(16) __half g_gw2[4*CHW];
__device__ __align__(16) __half g_mw1[3*CHW];
__device__ __align__(16) __half g_mw2[4*CHW];

__device__ __forceinline__ uint32_t smem_u32(const void* p) {
    uint32_t a;
    asm("{ .reg .u64 t; cvta.to.shared.u64 t, %1; cvt.u32.u64 %0, t; }" : "=r"(a) : "l"(p));
    return a;
}
#define LDSM4(r0,r1,r2,r3,addr) \
    asm volatile("ldmatrix.sync.aligned.m8n8.x4.shared.b16 {%0,%1,%2,%3}, [%4];" \
        : "=r"(r0),"=r"(r1),"=r"(r2),"=r"(r3) : "r"(addr))
#define MMA(d,a,b0,b1) \
    asm volatile("mma.sync.aligned.m16n8k16.row.col.f32.f16.f16.f32 " \
        "{%0,%1,%2,%3},{%4,%5,%6,%7},{%8,%9},{%0,%1,%2,%3};" \
        : "+f"((d)[0]),"+f"((d)[1]),"+f"((d)[2]),"+f"((d)[3]) \
        : "r"((a)[0]),"r"((a)[1]),"r"((a)[2]),"r"((a)[3]),"r"(b0),"r"(b1))
#define CP16(sa,gp) asm volatile("cp.async.cg.shared.global [%0], [%1], 16;" :: "r"(sa),"l"(gp))
#define CP_COMMIT() asm volatile("cp.async.commit_group;" ::: "memory")
#define CP_WAIT0()  asm volatile("cp.async.wait_group 0;" ::: "memory")
#define STS32(a,v)  asm volatile("st.shared.b32 [%0], %1;" :: "r"(a),"r"(v) : "memory")
#define STSV2(a,x,y) asm volatile("st.shared.v2.b32 [%0], {%1,%2};" :: "r"(a),"r"(x),"r"(y) : "memory")
#define REDH2V4(p,a,b,c,d) \
    asm volatile("red.global.add.noftz.v4.f16x2 [%0], {%1,%2,%3,%4};" \
        :: "l"(p), "r"(a), "r"(b), "r"(c), "r"(d) : "memory")
#define REDH2(p,a) \
    asm volatile("red.global.add.noftz.f16x2 [%0], %1;" :: "l"(p), "r"(a) : "memory")

__device__ __forceinline__ float sp(float x) {
    return fmaxf(x, 0.f) + __logf(1.f + __expf(-fabsf(x)));
}
__device__ __forceinline__ uint32_t pack2h(float a, float b) {
    __half2 h = __floats2half2_rn(a, b);
    return *(uint32_t*)&h;
}

// ---------------------------------------------------------------------------
__global__ void k_zero() {
    long long i = (long long)blockIdx.x * 256 + threadIdx.x;
    const long long P = (long long)M_SEG * PHSTR / 2;   // u32 words
    if (i < P) ((uint32_t*)g_pooled)[i] = 0u;
    else if (i < P + M_SEG) g_counts[i - P] = 0.f;
}

// one thread per (row, 8-half group); group 16 = frac + count
__global__ void k_accum(const float* __restrict__ emb, const float* __restrict__ frac,
                        const int* __restrict__ seg, float* __restrict__ out_frac) {
    int idx = blockIdx.x * 256 + threadIdx.x;
    if (idx >= N_ROWS * 17) return;
    int r = idx / 17;
    int g = idx - r * 17;
    int s = seg[r];
    if (g < 16) {
        const float4* e = (const float4*)&emb[(long long)r * EMB + g * 8];
        float4 a = e[0], b = e[1];
        REDH2V4(&g_pooled[(size_t)s * PHSTR + g * 8],
                pack2h(a.x, a.y), pack2h(a.z, a.w),
                pack2h(b.x, b.y), pack2h(b.z, b.w));
    } else {
        float f = frac[r];
        REDH2(&g_pooled[(size_t)s * PHSTR + 128], pack2h(f, 0.f));
        atomicAdd(&g_counts[s], 1.f);
        if (out_frac) out_frac[r] = f;
    }
}

// prep: W[Ksrc][256] -> chunk images [c][n][kk] fp16 RN (kk = 64 data + 8 pad)
__global__ void k_prep(const float* __restrict__ W, int mode, int nch, int Kreal, int which) {
    __half* dh;
    if (which == 0)      dh = g_gw1;
    else if (which == 1) dh = g_gw2;
    else if (which == 2) dh = g_mw1;
    else                 dh = g_mw2;
    int idx = blockIdx.x * 256 + threadIdx.x;
    if (idx >= nch * CHW) return;
    int c = idx / CHW, rem = idx - c * CHW;
    int n = rem / 72, kk = rem - n * 72;
    float v = 0.f;
    if (kk < 64) {
        int kg = c * 64 + kk, sr;
        if (mode == 1) sr = kg < 128 ? kg : (kg < 384 ? kg + 1 : (kg == 384 ? 128 : -1));
        else           sr = (kg < Kreal) ? kg : -1;
        if (sr >= 0) v = W[(long long)sr * 256 + n];
    }
    dh[idx] = __float2half_rn(v);
}

// ---------------------------------------------------------------------------
__device__ __forceinline__ void cp_chunk(uint32_t dst, const __half* src, int c, int tid) {
    const uint4* gp = (const uint4*)src + (long long)c * (CHW / 8);
#pragma unroll
    for (int j = 0; j < 9; j++) {
        int i = tid + j * 256;
        CP16(dst + i * 16, gp + i);
    }
}

// fp16 MMA over one 64-wide K chunk; warp tile 32x128; B stride 144B
__device__ __forceinline__ void mma_chunk(float (&acc)[2][16][4],
                                          uint32_t aBase, int aStride,
                                          uint32_t bBase,
                                          int lane, int m0, int n0w) {
    const int arow = (lane & 7) + ((lane >> 3) & 1) * 8;
    const int brow = (lane & 7) + (lane >> 4) * 8;
    const int bk0  = ((lane >> 3) & 1) * 16;
#pragma unroll
    for (int ks = 0; ks < 4; ks++) {
        uint32_t ah[2][4];
        int akb = ks * 32 + (lane >> 4) * 16;
#pragma unroll
        for (int mi = 0; mi < 2; mi++) {
            uint32_t ra = aBase + (uint32_t)(m0 + mi * 16 + arow) * aStride + akb;
            LDSM4(ah[mi][0], ah[mi][1], ah[mi][2], ah[mi][3], ra);
        }
        int bkb = ks * 32 + bk0;
#pragma unroll
        for (int g = 0; g < 8; g++) {
            uint32_t bh[4];
            uint32_t ro = (uint32_t)(n0w + g * 16 + brow) * 144 + bkb;
            LDSM4(bh[0], bh[1], bh[2], bh[3], bBase + ro);
#pragma unroll
            for (int mi = 0; mi < 2; mi++) {
                MMA(acc[mi][2*g],   ah[mi], bh[0], bh[1]);
                MMA(acc[mi][2*g+1], ah[mi], bh[2], bh[3]);
            }
        }
    }
}

template<int GATE>
__global__ __launch_bounds__(256, 1)
void k_mlp(const float* __restrict__ emb, const float* __restrict__ frac,
           const int* __restrict__ seg,
           const float* __restrict__ b1v, const float* __restrict__ b2v,
           float* __restrict__ outp) {
    extern __shared__ __align__(16) char sm[];
    const uint32_t sb = smem_u32(sm);
    const int tid = threadIdx.x, w = tid >> 5, lane = tid & 31;
    const int m0 = (w & 3) * 32, n0w = (w >> 2) * 128;
    const int rowBase = blockIdx.x * 128;
    constexpr int CH1 = GATE ? 7 : 3;   // both odd
    constexpr int CH2 = 4;

    float* bias1s = (float*)(sm + OFF_B1S);
    float* bias2s = (float*)(sm + OFF_B2S);
    int*   axseg  = (int*)  (sm + OFF_AUX);
    float* axinv  = (float*)(sm + OFF_AUX);

    bias1s[tid] = b1v[tid];
    bias2s[tid] = b2v[tid];
    if (tid < 128) {
        if (GATE) axseg[tid] = seg[rowBase + tid];
        else {
            int gr = rowBase + tid;
            float c = (gr < M_SEG) ? g_counts[gr] : 1.f;
            axinv[tid] = 1.f / fmaxf(c, 1.f);
        }
    }
    __syncthreads();   // axseg/axinv visible for gathers

    const __half* w1 = GATE ? g_gw1 : g_mw1;
    const __half* w2 = GATE ? g_gw2 : g_mw2;

    // gather one 64-wide A chunk into 16 packed-half2 regs
    const int gr_ = tid >> 1, ghalf = tid & 1;
    const int rg = rowBase + gr_;
    const int kk0 = ghalf * 32;
    auto gather = [&](int c, uint32_t (&ar)[16]) {
#pragma unroll
        for (int i = 0; i < 8; i++) {
            int kk = kk0 + i * 4;
            int k = c * 64 + kk;
            float4 v = make_float4(0.f, 0.f, 0.f, 0.f);
            if (GATE) {
                if (c < 2) v = *(const float4*)&emb[(long long)rg * EMB + k];
                else if (c < 6) {
                    int s = axseg[gr_];
                    v = *(const float4*)&g_ctx[(long long)s * CTX + (k - 128)];
                } else if (kk == 0) v.x = frac[rg];
            } else {
                if (rg < M_SEG) {
                    float inv = axinv[gr_];
                    if (c < 2) {
                        const __half2* hp = (const __half2*)&g_pooled[(size_t)rg * PHSTR + k];
                        __half2 x01 = hp[0], x23 = hp[1];
                        float2 f01 = __half22float2(x01), f23 = __half22float2(x23);
                        v = make_float4(f01.x * inv, f01.y * inv, f23.x * inv, f23.y * inv);
                    } else if (kk == 0) {
                        v.x = __half2float(g_pooled[(size_t)rg * PHSTR + 128]) * inv;
                    }
                }
            }
            ar[2*i]   = pack2h(v.x, v.y);
            ar[2*i+1] = pack2h(v.z, v.w);
        }
    };
    auto stsA = [&](uint32_t abuf, const uint32_t (&ar)[16]) {
        uint32_t base = abuf + (uint32_t)gr_ * 144 + (uint32_t)kk0 * 2;
#pragma unroll
        for (int i = 0; i < 8; i++)
            STSV2(base + i * 8, ar[2*i], ar[2*i+1]);
    };

    float acc[2][16][4];
#pragma unroll
    for (int i = 0; i < 2; i++)
#pragma unroll
        for (int j = 0; j < 16; j++)
#pragma unroll
            for (int q = 0; q < 4; q++) acc[i][j][q] = 0.f;

    // ---------------- phase 1: 1 sync per chunk, A+B double-buffered --------
    {
        uint32_t ar[16];
        gather(0, ar);
        stsA(sb + OFF_A10, ar);
        cp_chunk(sb + OFF_BB0, w1, 0, tid);
        CP_COMMIT();
    }
    for (int c = 0; c < CH1; ++c) {
        uint32_t ar[16];
        if (c + 1 < CH1) gather(c + 1, ar);           // LDGs in flight
        CP_WAIT0();                                   // B[c] arrived
        __syncthreads();                              // A[c] STS + B[c] visible
        if (c + 1 < CH1) {
            cp_chunk(sb + (((c + 1) & 1) ? OFF_BB1 : OFF_BB0), w1, c + 1, tid);
            CP_COMMIT();
        }
        mma_chunk(acc, sb + ((c & 1) ? OFF_A11 : OFF_A10), 144,
                  sb + ((c & 1) ? OFF_BB1 : OFF_BB0), lane, m0, n0w);
        if (c + 1 < CH1) stsA(sb + (((c + 1) & 1) ? OFF_A11 : OFF_A10), ar);
    }
    __syncthreads();   // all mma done before A2 overwrites A1 region

    // prefetch phase-2 chunk 0 (CH1 odd -> last B buf used was BB0)
    cp_chunk(sb + OFF_BB1, w2, 0, tid);
    CP_COMMIT();

    // ---------------- epilogue 1: acc -> softplus -> A2 fp16 ----------------
    {
        const int rb = m0 + (lane >> 2);
        const int cb = n0w + (lane & 3) * 2;
#pragma unroll
        for (int mi = 0; mi < 2; mi++)
#pragma unroll
            for (int ni = 0; ni < 16; ni++) {
                int col = cb + ni * 8;
                float2 bb = *(float2*)&bias1s[col];
                int row = rb + mi * 16;
                uint32_t ad = sb + OFF_A2 + (uint32_t)row * 528 + (uint32_t)col * 2;
                float y0 = sp(acc[mi][ni][0] + bb.x), y1 = sp(acc[mi][ni][1] + bb.y);
                STS32(ad, pack2h(y0, y1));
                float y2 = sp(acc[mi][ni][2] + bb.x), y3 = sp(acc[mi][ni][3] + bb.y);
                STS32(ad + 8 * 528, pack2h(y2, y3));
                acc[mi][ni][0] = acc[mi][ni][1] = acc[mi][ni][2] = acc[mi][ni][3] = 0.f;
            }
    }

    // ---------------- phase 2: B double-buffered, parity continues ----------
    for (int c = 0; c < CH2; ++c) {
        CP_WAIT0();
        __syncthreads();   // iter0: epilogue-1 STS visible; iterN: B reuse safe
        if (c + 1 < CH2) {
            cp_chunk(sb + (((CH1 + c + 1) & 1) ? OFF_BB1 : OFF_BB0), w2, c + 1, tid);
            CP_COMMIT();
        }
        mma_chunk(acc, sb + OFF_A2 + (uint32_t)c * 128, 528,
                  sb + (((CH1 + c) & 1) ? OFF_BB1 : OFF_BB0), lane, m0, n0w);
    }

    // ---------------- epilogue 2: acc -> softplus -> out --------------------
    {
        float* dst = GATE ? outp : g_ctx;
        const int rb = m0 + (lane >> 2);
        const int cb = n0w + (lane & 3) * 2;
#pragma unroll
        for (int mi = 0; mi < 2; mi++)
#pragma unroll
            for (int ni = 0; ni < 16; ni++) {
                int col = cb + ni * 8;
                float2 bb = *(float2*)&bias2s[col];
                int row = rb + mi * 16;
                int gr = rowBase + row;
                float y0 = sp(acc[mi][ni][0] + bb.x), y1 = sp(acc[mi][ni][1] + bb.y);
                if (GATE || gr < M_SEG)
                    *(float2*)&dst[(long long)gr * 256 + col] = make_float2(y0, y1);
                float y2 = sp(acc[mi][ni][2] + bb.x), y3 = sp(acc[mi][ni][3] + bb.y);
                if (GATE || gr + 8 < M_SEG)
                    *(float2*)&dst[(long long)(gr + 8) * 256 + col] = make_float2(y2, y3);
            }
    }
}

// ---------------------------------------------------------------------------
extern "C" void kernel_launch(void* const* d_in, const int* in_sizes, int n_in,
                              void* d_out, int out_size) {
    const float* emb  = (const float*)d_in[0];
    const float* frac = (const float*)d_in[1];
    const int*   seg  = (const int*)  d_in[2];
    const float* iW1  = (const float*)d_in[3];
    const float* ib1  = (const float*)d_in[4];
    const float* iW2  = (const float*)d_in[5];
    const float* ib2  = (const float*)d_in[6];
    const float* gW1  = (const float*)d_in[7];
    const float* gb1  = (const float*)d_in[8];
    const float* gW2  = (const float*)d_in[9];
    const float* gb2  = (const float*)d_in[10];
    float* out = (float*)d_out;

    cudaFuncSetAttribute(k_mlp<0>, cudaFuncAttributeMaxDynamicSharedMemorySize, SMEM_TOTAL);
    cudaFuncSetAttribute(k_mlp<1>, cudaFuncAttributeMaxDynamicSharedMemorySize, SMEM_TOTAL);

    k_prep<<<(7*CHW + 255)/256, 256>>>(gW1, 1, 7, 385, 0);
    k_prep<<<(4*CHW + 255)/256, 256>>>(gW2, 0, 4, 256, 1);
    k_prep<<<(3*CHW + 255)/256, 256>>>(iW1, 0, 3, 129, 2);
    k_prep<<<(4*CHW + 255)/256, 256>>>(iW2, 0, 4, 256, 3);

    long long totz = (long long)M_SEG * PHSTR / 2 + M_SEG;
    k_zero<<<(unsigned)((totz + 255)/256), 256>>>();

    float* out_frac = nullptr;
    if ((long long)out_size >= (long long)N_ROWS * (LAT + 1))
        out_frac = out + (size_t)N_ROWS * LAT;
    long long tota = (long long)N_ROWS * 17;
    k_accum<<<(unsigned)((tota + 255)/256), 256>>>(emb, frac, seg, out_frac);

    k_mlp<0><<<(M_SEG + 127)/128, 256, SMEM_TOTAL>>>(emb, frac, seg, ib1, ib2, nullptr);
    k_mlp<1><<<N_ROWS / 128, 256, SMEM_TOTAL>>>(emb, frac, seg, gb1, gb2, out);
}

// round 10
// speedup vs baseline: 6.0208x; 1.1563x over previous
#include <cuda_runtime.h>
#include <cuda_fp16.h>
#include <cstdint>
#include <math.h>

#define N_ROWS 400000
#define M_SEG  100000
#define EMB    128
#define CTX    256
#define LAT    256
#define PHSTR  136           // pooled row stride in halves

// smem layout (bytes)
#define OFF_B1S   0          // bias1: 256 f32
#define OFF_B2S   1024       // bias2: 256 f32
#define OFF_AUX   2048       // axseg/axinv 128 x 4B
#define OFF_FRS   2560       // fracs: 128 f32 (gate)
#define OFF_WFR   3072       // wfrac: 256 f32 (gate)
#define OFF_A2    4096       // A2: 128 x 528B = 67584 -> 71680
#define OFF_A10   4096       // A1 buf0 (aliases A2 region)
#define OFF_A11   22528      // A1 buf1
#define OFF_BB0   71680      // B buf0: 36864
#define OFF_BB1   108544     // B buf1: 36864 -> 145408
#define SMEM_TOTAL 145408

#define CHW 18432            // halves per 64-wide B chunk image (256 x 72)

// scratch globals
__device__ __align__(16) __half g_pooled[(size_t)M_SEG * PHSTR];
__device__ float g_counts[M_SEG];
__device__ float g_ctxpre[(size_t)M_SEG * CTX];   // ctx @ gW1[129:385], fp32
// prepped B chunk images: [chunk][256][72] fp16 RN
__device__ __align__(16) __half g_gwe[2*CHW];   // gate W1 rows 0..127
__device__ __align__(16) __half g_gwc[4*CHW];   // gate W1 rows 129..384 (ctx part)
__device__ __align__(16) __half g_gw2[4*CHW];
__device__ __align__(16) __half g_mw1[3*CHW];   // incl frac row at k=128
__device__ __align__(16) __half g_mw2[4*CHW];

__device__ __forceinline__ uint32_t smem_u32(const void* p) {
    uint32_t a;
    asm("{ .reg .u64 t; cvta.to.shared.u64 t, %1; cvt.u32.u64 %0, t; }" : "=r"(a) : "l"(p));
    return a;
}
#define LDSM4(r0,r1,r2,r3,addr) \
    asm volatile("ldmatrix.sync.aligned.m8n8.x4.shared.b16 {%0,%1,%2,%3}, [%4];" \
        : "=r"(r0),"=r"(r1),"=r"(r2),"=r"(r3) : "r"(addr))
#define MMA(d,a,b0,b1) \
    asm volatile("mma.sync.aligned.m16n8k16.row.col.f32.f16.f16.f32 " \
        "{%0,%1,%2,%3},{%4,%5,%6,%7},{%8,%9},{%0,%1,%2,%3};" \
        : "+f"((d)[0]),"+f"((d)[1]),"+f"((d)[2]),"+f"((d)[3]) \
        : "r"((a)[0]),"r"((a)[1]),"r"((a)[2]),"r"((a)[3]),"r"(b0),"r"(b1))
#define CP16(sa,gp) asm volatile("cp.async.cg.shared.global [%0], [%1], 16;" :: "r"(sa),"l"(gp))
#define CP_COMMIT() asm volatile("cp.async.commit_group;" ::: "memory")
#define CP_WAIT0()  asm volatile("cp.async.wait_group 0;" ::: "memory")
#define STS32(a,v)  asm volatile("st.shared.b32 [%0], %1;" :: "r"(a),"r"(v) : "memory")
#define STSV2(a,x,y) asm volatile("st.shared.v2.b32 [%0], {%1,%2};" :: "r"(a),"r"(x),"r"(y) : "memory")
#define REDH2V4(p,a,b,c,d) \
    asm volatile("red.global.add.noftz.v4.f16x2 [%0], {%1,%2,%3,%4};" \
        :: "l"(p), "r"(a), "r"(b), "r"(c), "r"(d) : "memory")
#define REDH2(p,a) \
    asm volatile("red.global.add.noftz.f16x2 [%0], %1;" :: "l"(p), "r"(a) : "memory")

__device__ __forceinline__ float sp(float x) {
    return fmaxf(x, 0.f) + __logf(1.f + __expf(-fabsf(x)));
}
__device__ __forceinline__ uint32_t pack2h(float a, float b) {
    __half2 h = __floats2half2_rn(a, b);
    return *(uint32_t*)&h;
}

// ---------------------------------------------------------------------------
__global__ void k_zero() {
    long long i = (long long)blockIdx.x * 256 + threadIdx.x;
    const long long P = (long long)M_SEG * PHSTR / 2;
    if (i < P) ((uint32_t*)g_pooled)[i] = 0u;
    else if (i < P + M_SEG) g_counts[i - P] = 0.f;
}

__global__ void k_accum(const float* __restrict__ emb, const float* __restrict__ frac,
                        const int* __restrict__ seg, float* __restrict__ out_frac) {
    int idx = blockIdx.x * 256 + threadIdx.x;
    if (idx >= N_ROWS * 17) return;
    int r = idx / 17;
    int g = idx - r * 17;
    int s = seg[r];
    if (g < 16) {
        const float4* e = (const float4*)&emb[(long long)r * EMB + g * 8];
        float4 a = e[0], b = e[1];
        REDH2V4(&g_pooled[(size_t)s * PHSTR + g * 8],
                pack2h(a.x, a.y), pack2h(a.z, a.w),
                pack2h(b.x, b.y), pack2h(b.z, b.w));
    } else {
        float f = frac[r];
        REDH2(&g_pooled[(size_t)s * PHSTR + 128], pack2h(f, 0.f));
        atomicAdd(&g_counts[s], 1.f);
        if (out_frac) out_frac[r] = f;
    }
}

// prep: W -> chunk images [c][n][72] fp16 RN. mode 0: rows 0..Kreal-1.
// mode 2: rows 129..384 of gW1 (ctx block).
__global__ void k_prep(const float* __restrict__ W, int mode, int nch, int Kreal, int which) {
    __half* dh;
    if (which == 0)      dh = g_gwe;
    else if (which == 1) dh = g_gwc;
    else if (which == 2) dh = g_gw2;
    else if (which == 3) dh = g_mw1;
    else                 dh = g_mw2;
    int idx = blockIdx.x * 256 + threadIdx.x;
    if (idx >= nch * CHW) return;
    int c = idx / CHW, rem = idx - c * CHW;
    int n = rem / 72, kk = rem - n * 72;
    float v = 0.f;
    if (kk < 64) {
        int kg = c * 64 + kk, sr;
        if (mode == 2) sr = (kg < 256) ? kg + 129 : -1;
        else           sr = (kg < Kreal) ? kg : -1;
        if (sr >= 0) v = W[(long long)sr * 256 + n];
    }
    dh[idx] = __float2half_rn(v);
}

// ---------------------------------------------------------------------------
__device__ __forceinline__ void cp_chunk(uint32_t dst, const __half* src, int c, int tid) {
    const uint4* gp = (const uint4*)src + (long long)c * (CHW / 8);
#pragma unroll
    for (int j = 0; j < 9; j++) {
        int i = tid + j * 256;
        CP16(dst + i * 16, gp + i);
    }
}

__device__ __forceinline__ void mma_chunk(float (&acc)[2][16][4],
                                          uint32_t aBase, int aStride,
                                          uint32_t bBase,
                                          int lane, int m0, int n0w) {
    const int arow = (lane & 7) + ((lane >> 3) & 1) * 8;
    const int brow = (lane & 7) + (lane >> 4) * 8;
    const int bk0  = ((lane >> 3) & 1) * 16;
#pragma unroll
    for (int ks = 0; ks < 4; ks++) {
        uint32_t ah[2][4];
        int akb = ks * 32 + (lane >> 4) * 16;
#pragma unroll
        for (int mi = 0; mi < 2; mi++) {
            uint32_t ra = aBase + (uint32_t)(m0 + mi * 16 + arow) * aStride + akb;
            LDSM4(ah[mi][0], ah[mi][1], ah[mi][2], ah[mi][3], ra);
        }
        int bkb = ks * 32 + bk0;
#pragma unroll
        for (int g = 0; g < 8; g++) {
            uint32_t bh[4];
            uint32_t ro = (uint32_t)(n0w + g * 16 + brow) * 144 + bkb;
            LDSM4(bh[0], bh[1], bh[2], bh[3], bBase + ro);
#pragma unroll
            for (int mi = 0; mi < 2; mi++) {
                MMA(acc[mi][2*g],   ah[mi], bh[0], bh[1]);
                MMA(acc[mi][2*g+1], ah[mi], bh[2], bh[3]);
            }
        }
    }
}

#define CLR_ACC() \
    _Pragma("unroll") for (int i_ = 0; i_ < 2; i_++) \
    _Pragma("unroll") for (int j_ = 0; j_ < 16; j_++) \
    _Pragma("unroll") for (int q_ = 0; q_ < 4; q_++) acc[i_][j_][q_] = 0.f

// ---------------------------------------------------------------------------
// mix: pooled mean -> L1 -> L2 (ctx) -> L3 (ctx @ gWc) -> g_ctxpre (fp32)
__global__ __launch_bounds__(256, 1)
void k_mix(const float* __restrict__ b1v, const float* __restrict__ b2v) {
    extern __shared__ __align__(16) char sm[];
    const uint32_t sb = smem_u32(sm);
    const int tid = threadIdx.x, w = tid >> 5, lane = tid & 31;
    const int m0 = (w & 3) * 32, n0w = (w >> 2) * 128;
    const int rowBase = blockIdx.x * 128;

    float* bias1s = (float*)(sm + OFF_B1S);
    float* bias2s = (float*)(sm + OFF_B2S);
    float* axinv  = (float*)(sm + OFF_AUX);

    bias1s[tid] = b1v[tid];
    bias2s[tid] = b2v[tid];
    if (tid < 128) {
        int gr = rowBase + tid;
        float c = (gr < M_SEG) ? g_counts[gr] : 1.f;
        axinv[tid] = 1.f / fmaxf(c, 1.f);
    }
    __syncthreads();

    const int gr_ = tid >> 1, ghalf = tid & 1;
    const int rg = rowBase + gr_;
    const int kk0 = ghalf * 32;
    auto gather = [&](int c, uint32_t (&ar)[16]) {
#pragma unroll
        for (int i = 0; i < 8; i++) {
            int kk = kk0 + i * 4;
            int k = c * 64 + kk;
            float4 v = make_float4(0.f, 0.f, 0.f, 0.f);
            if (rg < M_SEG) {
                float inv = axinv[gr_];
                if (c < 2) {
                    const __half2* hp = (const __half2*)&g_pooled[(size_t)rg * PHSTR + k];
                    float2 f01 = __half22float2(hp[0]), f23 = __half22float2(hp[1]);
                    v = make_float4(f01.x * inv, f01.y * inv, f23.x * inv, f23.y * inv);
                } else if (kk == 0) {
                    v.x = __half2float(g_pooled[(size_t)rg * PHSTR + 128]) * inv;
                }
            }
            ar[2*i]   = pack2h(v.x, v.y);
            ar[2*i+1] = pack2h(v.z, v.w);
        }
    };
    auto stsA = [&](uint32_t abuf, const uint32_t (&ar)[16]) {
        uint32_t base = abuf + (uint32_t)gr_ * 144 + (uint32_t)kk0 * 2;
#pragma unroll
        for (int i = 0; i < 8; i++)
            STSV2(base + i * 8, ar[2*i], ar[2*i+1]);
    };

    float acc[2][16][4];
    CLR_ACC();
    const int rb = m0 + (lane >> 2);
    const int cb = n0w + (lane & 3) * 2;

    // -------- phase 1: 3 chunks (t=0,1,2) --------
    {
        uint32_t ar[16];
        gather(0, ar); stsA(sb + OFF_A10, ar);
        cp_chunk(sb + OFF_BB0, g_mw1, 0, tid); CP_COMMIT();
    }
    for (int c = 0; c < 3; ++c) {
        uint32_t ar[16];
        if (c + 1 < 3) gather(c + 1, ar);
        CP_WAIT0();
        __syncthreads();
        if (c + 1 < 3) { cp_chunk(sb + (((c+1)&1)?OFF_BB1:OFF_BB0), g_mw1, c+1, tid); CP_COMMIT(); }
        mma_chunk(acc, sb + ((c&1)?OFF_A11:OFF_A10), 144,
                  sb + ((c&1)?OFF_BB1:OFF_BB0), lane, m0, n0w);
        if (c + 1 < 3) stsA(sb + (((c+1)&1)?OFF_A11:OFF_A10), ar);
    }
    __syncthreads();
    cp_chunk(sb + OFF_BB1, g_mw2, 0, tid); CP_COMMIT();   // t=3 -> BB1

    // epi1 -> A2
#pragma unroll
    for (int mi = 0; mi < 2; mi++)
#pragma unroll
        for (int ni = 0; ni < 16; ni++) {
            int col = cb + ni * 8;
            float2 bb = *(float2*)&bias1s[col];
            int row = rb + mi * 16;
            uint32_t ad = sb + OFF_A2 + (uint32_t)row * 528 + (uint32_t)col * 2;
            STS32(ad, pack2h(sp(acc[mi][ni][0]+bb.x), sp(acc[mi][ni][1]+bb.y)));
            STS32(ad + 8*528, pack2h(sp(acc[mi][ni][2]+bb.x), sp(acc[mi][ni][3]+bb.y)));
        }
    CLR_ACC();

    // -------- phase 2: 4 chunks (t=3..6), buf parity (c+1)&1 --------
    for (int c = 0; c < 4; ++c) {
        CP_WAIT0();
        __syncthreads();
        if (c + 1 < 4) { cp_chunk(sb + ((c&1)?OFF_BB1:OFF_BB0), g_mw2, c+1, tid); CP_COMMIT(); }
        else           { cp_chunk(sb + OFF_BB1, g_gwc, 0, tid); CP_COMMIT(); }   // t=7 -> BB1
        mma_chunk(acc, sb + OFF_A2 + (uint32_t)c * 128, 528,
                  sb + (((c+1)&1)?OFF_BB1:OFF_BB0), lane, m0, n0w);
    }
    __syncthreads();   // A2 rewrite hazard

    // epi2 -> A3 (ctx, fp16, same A2 region)
#pragma unroll
    for (int mi = 0; mi < 2; mi++)
#pragma unroll
        for (int ni = 0; ni < 16; ni++) {
            int col = cb + ni * 8;
            float2 bb = *(float2*)&bias2s[col];
            int row = rb + mi * 16;
            uint32_t ad = sb + OFF_A2 + (uint32_t)row * 528 + (uint32_t)col * 2;
            STS32(ad, pack2h(sp(acc[mi][ni][0]+bb.x), sp(acc[mi][ni][1]+bb.y)));
            STS32(ad + 8*528, pack2h(sp(acc[mi][ni][2]+bb.x), sp(acc[mi][ni][3]+bb.y)));
        }
    CLR_ACC();

    // -------- phase 3: 4 chunks (t=7..10), buf parity (c+1)&1 --------
    for (int c = 0; c < 4; ++c) {
        CP_WAIT0();
        __syncthreads();
        if (c + 1 < 4) { cp_chunk(sb + ((c&1)?OFF_BB1:OFF_BB0), g_gwc, c+1, tid); CP_COMMIT(); }
        mma_chunk(acc, sb + OFF_A2 + (uint32_t)c * 128, 528,
                  sb + (((c+1)&1)?OFF_BB1:OFF_BB0), lane, m0, n0w);
    }

    // epi3 -> g_ctxpre (fp32, no bias/activation)
#pragma unroll
    for (int mi = 0; mi < 2; mi++)
#pragma unroll
        for (int ni = 0; ni < 16; ni++) {
            int col = cb + ni * 8;
            int gr = rowBase + rb + mi * 16;
            if (gr < M_SEG)
                *(float2*)&g_ctxpre[(size_t)gr * 256 + col] =
                    make_float2(acc[mi][ni][0], acc[mi][ni][1]);
            if (gr + 8 < M_SEG)
                *(float2*)&g_ctxpre[(size_t)(gr+8) * 256 + col] =
                    make_float2(acc[mi][ni][2], acc[mi][ni][3]);
        }
}

// ---------------------------------------------------------------------------
// gate: emb-only L1 (2 chunks) + ctxpre[seg] + frac*w128 -> softplus -> L2 -> out
__global__ __launch_bounds__(256, 1)
void k_gate(const float* __restrict__ emb, const float* __restrict__ frac,
            const int* __restrict__ seg, const float* __restrict__ gW1,
            const float* __restrict__ b1v, const float* __restrict__ b2v,
            float* __restrict__ outp) {
    extern __shared__ __align__(16) char sm[];
    const uint32_t sb = smem_u32(sm);
    const int tid = threadIdx.x, w = tid >> 5, lane = tid & 31;
    const int m0 = (w & 3) * 32, n0w = (w >> 2) * 128;
    const int rowBase = blockIdx.x * 128;

    float* bias1s = (float*)(sm + OFF_B1S);
    float* bias2s = (float*)(sm + OFF_B2S);
    int*   axseg  = (int*)  (sm + OFF_AUX);
    float* fracs  = (float*)(sm + OFF_FRS);
    float* wfrac  = (float*)(sm + OFF_WFR);

    bias1s[tid] = b1v[tid];
    bias2s[tid] = b2v[tid];
    wfrac[tid]  = gW1[128 * 256 + tid];
    if (tid < 128) {
        axseg[tid] = seg[rowBase + tid];
        fracs[tid] = frac[rowBase + tid];
    }
    __syncthreads();

    const int gr_ = tid >> 1, ghalf = tid & 1;
    const int rg = rowBase + gr_;
    const int kk0 = ghalf * 32;
    auto gatherE = [&](int c, uint32_t (&ar)[16]) {
#pragma unroll
        for (int i = 0; i < 8; i++) {
            int kk = kk0 + i * 4;
            float4 v = *(const float4*)&emb[(long long)rg * EMB + c * 64 + kk];
            ar[2*i]   = pack2h(v.x, v.y);
            ar[2*i+1] = pack2h(v.z, v.w);
        }
    };
    auto stsA = [&](uint32_t abuf, const uint32_t (&ar)[16]) {
        uint32_t base = abuf + (uint32_t)gr_ * 144 + (uint32_t)kk0 * 2;
#pragma unroll
        for (int i = 0; i < 8; i++)
            STSV2(base + i * 8, ar[2*i], ar[2*i+1]);
    };

    float acc[2][16][4];
    CLR_ACC();
    const int rb = m0 + (lane >> 2);
    const int cb = n0w + (lane & 3) * 2;

    // -------- phase 1: 2 chunks (t=0,1) --------
    {
        uint32_t ar[16];
        gatherE(0, ar); stsA(sb + OFF_A10, ar);
        cp_chunk(sb + OFF_BB0, g_gwe, 0, tid); CP_COMMIT();
    }
    for (int c = 0; c < 2; ++c) {
        uint32_t ar[16];
        if (c + 1 < 2) gatherE(c + 1, ar);
        CP_WAIT0();
        __syncthreads();
        if (c + 1 < 2) { cp_chunk(sb + OFF_BB1, g_gwe, 1, tid); CP_COMMIT(); }
        mma_chunk(acc, sb + ((c&1)?OFF_A11:OFF_A10), 144,
                  sb + ((c&1)?OFF_BB1:OFF_BB0), lane, m0, n0w);
        if (c + 1 < 2) stsA(sb + OFF_A11, ar);
    }
    __syncthreads();
    cp_chunk(sb + OFF_BB0, g_gw2, 0, tid); CP_COMMIT();   // t=2 -> BB0

    // epi1: acc += ctxpre[seg] + frac*wfrac, + b1 -> softplus -> A2
    {
        int sgl[4]; float fr[4];
#pragma unroll
        for (int q = 0; q < 4; q++) {
            int row = rb + (q >> 1) * 16 + (q & 1) * 8;
            sgl[q] = axseg[row];
            fr[q]  = fracs[row];
        }
#pragma unroll
        for (int mi = 0; mi < 2; mi++)
#pragma unroll
            for (int ni = 0; ni < 16; ni++) {
                int col = cb + ni * 8;
                float2 bb = *(float2*)&bias1s[col];
                float2 wf = *(float2*)&wfrac[col];
                float2 c0 = *(const float2*)&g_ctxpre[(size_t)sgl[mi*2]   * 256 + col];
                float2 c1 = *(const float2*)&g_ctxpre[(size_t)sgl[mi*2+1] * 256 + col];
                int row = rb + mi * 16;
                uint32_t ad = sb + OFF_A2 + (uint32_t)row * 528 + (uint32_t)col * 2;
                float y0 = sp(acc[mi][ni][0] + c0.x + fr[mi*2]*wf.x + bb.x);
                float y1 = sp(acc[mi][ni][1] + c0.y + fr[mi*2]*wf.y + bb.y);
                STS32(ad, pack2h(y0, y1));
                float y2 = sp(acc[mi][ni][2] + c1.x + fr[mi*2+1]*wf.x + bb.x);
                float y3 = sp(acc[mi][ni][3] + c1.y + fr[mi*2+1]*wf.y + bb.y);
                STS32(ad + 8*528, pack2h(y2, y3));
            }
    }
    CLR_ACC();

    // -------- phase 2: 4 chunks (t=2..5), buf parity c&1 --------
    for (int c = 0; c < 4; ++c) {
        CP_WAIT0();
        __syncthreads();
        if (c + 1 < 4) { cp_chunk(sb + (((c+1)&1)?OFF_BB1:OFF_BB0), g_gw2, c+1, tid); CP_COMMIT(); }
        mma_chunk(acc, sb + OFF_A2 + (uint32_t)c * 128, 528,
                  sb + ((c&1)?OFF_BB1:OFF_BB0), lane, m0, n0w);
    }

    // epi2 -> out
#pragma unroll
    for (int mi = 0; mi < 2; mi++)
#pragma unroll
        for (int ni = 0; ni < 16; ni++) {
            int col = cb + ni * 8;
            float2 bb = *(float2*)&bias2s[col];
            int gr = rowBase + rb + mi * 16;
            *(float2*)&outp[(long long)gr * 256 + col] =
                make_float2(sp(acc[mi][ni][0]+bb.x), sp(acc[mi][ni][1]+bb.y));
            *(float2*)&outp[(long long)(gr+8) * 256 + col] =
                make_float2(sp(acc[mi][ni][2]+bb.x), sp(acc[mi][ni][3]+bb.y));
        }
}

// ---------------------------------------------------------------------------
extern "C" void kernel_launch(void* const* d_in, const int* in_sizes, int n_in,
                              void* d_out, int out_size) {
    const float* emb  = (const float*)d_in[0];
    const float* frac = (const float*)d_in[1];
    const int*   seg  = (const int*)  d_in[2];
    const float* iW1  = (const float*)d_in[3];
    const float* ib1  = (const float*)d_in[4];
    const float* iW2  = (const float*)d_in[5];
    const float* ib2  = (const float*)d_in[6];
    const float* gW1  = (const float*)d_in[7];
    const float* gb1  = (const float*)d_in[8];
    const float* gW2  = (const float*)d_in[9];
    const float* gb2  = (const float*)d_in[10];
    float* out = (float*)d_out;

    cudaFuncSetAttribute(k_mix,  cudaFuncAttributeMaxDynamicSharedMemorySize, SMEM_TOTAL);
    cudaFuncSetAttribute(k_gate, cudaFuncAttributeMaxDynamicSharedMemorySize, SMEM_TOTAL);

    k_prep<<<(2*CHW + 255)/256, 256>>>(gW1, 0, 2, 128, 0);   // g_gwe
    k_prep<<<(4*CHW + 255)/256, 256>>>(gW1, 2, 4, 256, 1);   // g_gwc
    k_prep<<<(4*CHW + 255)/256, 256>>>(gW2, 0, 4, 256, 2);   // g_gw2
    k_prep<<<(3*CHW + 255)/256, 256>>>(iW1, 0, 3, 129, 3);   // g_mw1
    k_prep<<<(4*CHW + 255)/256, 256>>>(iW2, 0, 4, 256, 4);   // g_mw2

    long long totz = (long long)M_SEG * PHSTR / 2 + M_SEG;
    k_zero<<<(unsigned)((totz + 255)/256), 256>>>();

    float* out_frac = nullptr;
    if ((long long)out_size >= (long long)N_ROWS * (LAT + 1))
        out_frac = out + (size_t)N_ROWS * LAT;
    long long tota = (long long)N_ROWS * 17;
    k_accum<<<(unsigned)((tota + 255)/256), 256>>>(emb, frac, seg, out_frac);

    k_mix<<<(M_SEG + 127)/128, 256, SMEM_TOTAL>>>(ib1, ib2);
    k_gate<<<N_ROWS / 128, 256, SMEM_TOTAL>>>(emb, frac, seg, gW1, gb1, gb2, out);
}